// round 8
// baseline (speedup 1.0000x reference)
#include <cuda_runtime.h>
#include <math.h>

#define NB 64
#define HH 30
#define WW 60
#define DD 64

// ---------------- scratch (device globals; no allocation) ----------------
__device__ float g_part[NB*16*16*DD];     // per-block partial cell sums (4 MB)
__device__ float g_dvec[NB*8*16*DD];      // dvec per (batch,hseg,combo) (2 MB)
__device__ float g_s[NB*128];             // raw s per (batch,hseg,combo)
__device__ unsigned g_cntA[NB*32];        // barrier-1 counters (monotonic, replay-safe)
__device__ unsigned g_cntB[NB*32];        // barrier-2 counters

// ---------------- geometry LUTs ----------------
__constant__ int c_wstart[16] = {0,6,10,12,15,18,20,24,30,36,40,42,45,48,50,54};
__constant__ int c_wlen[16]   = {6,4,2,3,3,2,4,6, 6,4,2,3,3,2,4,6};
__constant__ unsigned char c_hseg[30] = {
  0,0,0,0,0,0, 1,1,1,1, 2,2, 3,3,3, 4,4,4, 5,5, 6,6,6,6, 7,7,7,7,7,7};
__constant__ unsigned char c_wseg[60] = {
  0,0,0,0,0,0, 1,1,1,1, 2,2, 3,3,3, 4,4,4, 5,5, 6,6,6,6, 7,7,7,7,7,7,
  8,8,8,8,8,8, 9,9,9,9, 10,10, 11,11,11, 12,12,12, 13,13, 14,14,14,14,
  15,15,15,15,15,15};
// forward maps seg -> pool region index
__constant__ unsigned char c_rh0[8]  = {0,1,1,2,2,3,3,4};
__constant__ unsigned char c_rh1[8]  = {0,0,1,1,1,1,2,2};
__constant__ unsigned char c_rh2[8]  = {0,0,0,0,1,1,1,1};
__constant__ unsigned char c_rw0[16] = {0,1,1,2,2,3,3,4,5,6,6,7,7,8,8,9};
__constant__ unsigned char c_rw1[16] = {0,0,1,1,1,1,2,2,3,3,4,4,4,4,5,5};
__constant__ unsigned char c_rw2[16] = {0,0,0,0,1,1,1,1,2,2,2,2,3,3,3,3};
// inverse maps: region row/col -> [first seg, count]
__constant__ unsigned char p0_hf[5]={0,1,3,5,7},              p0_hc[5]={1,2,2,2,1};
__constant__ unsigned char p0_wf[10]={0,1,3,5,7,8,9,11,13,15},p0_wc[10]={1,2,2,2,1,1,2,2,2,1};
__constant__ unsigned char p1_hf[3]={0,2,6},                  p1_hc[3]={2,4,2};
__constant__ unsigned char p1_wf[6]={0,2,6,8,10,14},          p1_wc[6]={2,4,2,2,4,2};
__constant__ unsigned char p2_hf[2]={0,4},                    p2_hc[2]={4,4};
__constant__ unsigned char p2_wf[4]={0,4,8,12},               p2_wc[4]={4,4,4,4};
// hseg -> the two g_part slots that sum to its cells (zero-slots 1,9,15 pad cnt=1)
__constant__ unsigned char c_i1[8] = {0,3,5,7,8,10,11,13};
__constant__ unsigned char c_i2[8] = {2,4,6,1,9,15,12,14};

__device__ __forceinline__ void batch_barrier(unsigned* cnt, int tid) {
    __threadfence();                       // release this block's global stores
    __syncthreads();
    if (tid == 0) {
        unsigned o = atomicAdd(cnt, 1u);
        unsigned target = ((o >> 3) + 1u) << 3;   // next multiple of 8
        while ((int)(*(volatile unsigned*)cnt - target) < 0) { }
        __threadfence();                   // acquire
    }
    __syncthreads();
}

__device__ __forceinline__ float gumbel_mask(float attn, float nxv, float nrv) {
    float sig = 1.f / (1.f + expf(-attn));
    float gx  = logf(sig + 1e-8f);
    float gr  = logf(1.f - sig + 1e-8f);
    float nx  = -logf(-logf(nxv + 1e-8f) + 1e-8f);
    float nr  = -logf(-logf(nrv + 1e-8f) + 1e-8f);
    const float invT = 1.f / (0.03f + 1e-8f);
    float l = (gx + nx)*invT - (gr + nr)*invT;
    return 1.f / (1.f + expf(-l));
}

// ============ fused kernel: grid = 512 = (batch, k), one wave ============
__global__ __launch_bounds__(256, 4) void k_fused(
    const float* __restrict__ x,
    const float* __restrict__ qk_w,
    const float* __restrict__ qk_b,
    const float* __restrict__ score_w,
    const float* __restrict__ score_b,
    const float* __restrict__ noise_x,
    const float* __restrict__ noise_r,
    float* __restrict__ out)
{
    __shared__ __align__(16) float Asm[4096];    // Wq as-is:  A[e*64+j]
    __shared__ __align__(16) float Btsm[4096];   // Wk transposed: Bt[d*64+e]
    __shared__ __align__(16) float rs[20*64];    // region sums
    __shared__ __align__(16) float ush[16*64];   // u vectors; phase C: dvec(hsA)
    __shared__ __align__(16) float tsm[16*64];   // t vectors; phase C: dvec(hsB)
    __shared__ float qkb[128];
    __shared__ float bshC[32];

    int bi  = blockIdx.x;
    int b   = bi >> 3, k = bi & 7;
    int tid = threadIdx.x;
    int start = (k*30) >> 3;                 // balanced contiguous row ranges
    int end   = ((k+1)*30) >> 3;             // sizes 3,4,4,4,3,4,4,4
    int hsA = c_hseg[start];
    int hsB = c_hseg[end - 1];               // ranges span <= 2 hsegs (verified)

    // ---------------- phase A: balanced partial cell sums -------------------
    {
        int ws = tid >> 4, j = tid & 15;     // wseg 0..15, d-quad 0..15
        int a0 = c_wstart[ws], l0 = c_wlen[ws];
        const float4* xb4 = (const float4*)(x + (size_t)(b*HH) * WW * DD);
        float4 accA = make_float4(0.f,0.f,0.f,0.f);
        float4 accB = make_float4(0.f,0.f,0.f,0.f);
        #pragma unroll
        for (int r = 0; r < 4; r++) {
            int h = start + r;
            if (h < end) {
                const float4* xr = xb4 + (h*WW + a0)*16 + j;
                float4 t = make_float4(0.f,0.f,0.f,0.f);
                #pragma unroll
                for (int w = 0; w < 6; w++) {
                    if (w < l0) {
                        float4 v = xr[w*16];
                        t.x += v.x; t.y += v.y; t.z += v.z; t.w += v.w;
                    }
                }
                if ((int)c_hseg[h] == hsA) {
                    accA.x += t.x; accA.y += t.y; accA.z += t.z; accA.w += t.w;
                } else {
                    accB.x += t.x; accB.y += t.y; accB.z += t.z; accB.w += t.w;
                }
            }
        }
        float4* pp = (float4*)(g_part + ((size_t)b*16 + k*2) * 1024);
        pp[ws*16 + j]       = accA;          // slot k*2
        pp[256 + ws*16 + j] = accB;          // slot k*2+1 (zeros if single-hseg)
    }

    // ---- weight smem fill (overlaps A's tail; pre-barrier) ----
    for (int v = tid; v < 4096; v += 256) Asm[v] = qk_w[v];
    for (int v = tid; v < 4096; v += 256) {
        int e = v >> 6, d = v & 63;
        Btsm[d*64 + e] = qk_w[4096 + v];
    }
    if (tid < 128) qkb[tid] = qk_b[tid];

    batch_barrier(&g_cntA[b*32], tid);

    // ---------------- phase B: regions -> u -> t -> (s, dvec) ---------------
    // this block computes for hseg hs = k
    {
        int hs = k;
        const float* pb = g_part + (size_t)b * 16384;
        int rh0 = c_rh0[hs], rh1 = c_rh1[hs], rh2 = c_rh2[hs];
        for (int v = tid; v < 1280; v += 256) {
            int jj = v >> 6, d = v & 63;
            int hf, hc, wf, wc;
            if (jj < 10)      { hf=p0_hf[rh0]; hc=p0_hc[rh0]; wf=p0_wf[jj];   wc=p0_wc[jj]; }
            else if (jj < 16) { int rw=jj-10; hf=p1_hf[rh1]; hc=p1_hc[rh1]; wf=p1_wf[rw]; wc=p1_wc[rw]; }
            else              { int rw=jj-16; hf=p2_hf[rh2]; hc=p2_hc[rh2]; wf=p2_wf[rw]; wc=p2_wc[rw]; }
            float s = 0.f;
            for (int a = 0; a < hc; a++) {
                int hsr = hf + a;
                const float* p1 = pb + (int)c_i1[hsr]*1024;
                const float* p2 = pb + (int)c_i2[hsr]*1024;
                for (int c2 = 0; c2 < wc; c2++) {
                    int o = (wf + c2)*64 + d;
                    s += __ldcg(p1 + o) + __ldcg(p2 + o);
                }
            }
            rs[v] = s;
        }
        __syncthreads();

        float w0 = score_w[0], w1 = score_w[1], w2 = score_w[2];
        float a0 = w0*(1.f/36.f), a1 = w1*(1.f/100.f), a2 = w2*(1.f/225.f);
        float wsum = w0 + w1 + w2;

        for (int v = tid; v < 1024; v += 256) {
            int ws = v >> 6, f = v & 63;
            ush[v] = a0*rs[(int)c_rw0[ws]*64 + f]
                   + a1*rs[(10 + (int)c_rw1[ws])*64 + f]
                   + a2*rs[(16 + (int)c_rw2[ws])*64 + f];
        }
        __syncthreads();

        // t[c] = Wk u[c] + wsum*bk
        int e = tid & 63, cg = tid >> 6;
        {
            float init = wsum * qkb[64 + e];
            float t0 = init, t1 = init, t2 = init, t3 = init;
            const float4* u0 = (const float4*)(ush + (cg*4 + 0)*64);
            const float4* u1 = (const float4*)(ush + (cg*4 + 1)*64);
            const float4* u2 = (const float4*)(ush + (cg*4 + 2)*64);
            const float4* u3 = (const float4*)(ush + (cg*4 + 3)*64);
            #pragma unroll
            for (int fq = 0; fq < 16; fq++) {
                int d = fq*4;
                float m0 = Btsm[(d+0)*64 + e];
                float m1 = Btsm[(d+1)*64 + e];
                float m2 = Btsm[(d+2)*64 + e];
                float m3 = Btsm[(d+3)*64 + e];
                float4 ua = u0[fq], ub = u1[fq], uc = u2[fq], ud = u3[fq];
                t0 += m0*ua.x + m1*ua.y + m2*ua.z + m3*ua.w;
                t1 += m0*ub.x + m1*ub.y + m2*ub.z + m3*ub.w;
                t2 += m0*uc.x + m1*uc.y + m2*uc.z + m3*uc.w;
                t3 += m0*ud.x + m1*ud.y + m2*ud.z + m3*ud.w;
            }
            tsm[(cg*4 + 0)*64 + e] = t0;
            tsm[(cg*4 + 1)*64 + e] = t1;
            tsm[(cg*4 + 2)*64 + e] = t2;
            tsm[(cg*4 + 3)*64 + e] = t3;
        }
        __syncthreads();

        // s[c] = bq . t[c]   (raw, scaled in phase C)
        int lane = tid & 31, warp = tid >> 5;
        for (int c = warp; c < 16; c += 8) {
            float sv = tsm[c*64 + lane]      * qkb[lane]
                     + tsm[c*64 + 32 + lane] * qkb[32 + lane];
            #pragma unroll
            for (int o = 16; o; o >>= 1) sv += __shfl_xor_sync(0xffffffffu, sv, o);
            if (lane == 0) g_s[b*128 + hs*16 + c] = sv;
        }

        // dvec[c] = Wq^T t[c] -> global
        {
            int j = tid & 63;
            float d0 = 0.f, d1 = 0.f, d2 = 0.f, d3 = 0.f;
            const float4* t0p = (const float4*)(tsm + (cg*4 + 0)*64);
            const float4* t1p = (const float4*)(tsm + (cg*4 + 1)*64);
            const float4* t2p = (const float4*)(tsm + (cg*4 + 2)*64);
            const float4* t3p = (const float4*)(tsm + (cg*4 + 3)*64);
            #pragma unroll
            for (int eq = 0; eq < 16; eq++) {
                int ee = eq*4;
                float a0v = Asm[(ee+0)*64 + j];
                float a1v = Asm[(ee+1)*64 + j];
                float a2v = Asm[(ee+2)*64 + j];
                float a3v = Asm[(ee+3)*64 + j];
                float4 ta = t0p[eq], tb = t1p[eq], tc = t2p[eq], td = t3p[eq];
                d0 += a0v*ta.x + a1v*ta.y + a2v*ta.z + a3v*ta.w;
                d1 += a0v*tb.x + a1v*tb.y + a2v*tb.z + a3v*tb.w;
                d2 += a0v*tc.x + a1v*tc.y + a2v*tc.z + a3v*tc.w;
                d3 += a0v*td.x + a1v*td.y + a2v*td.z + a3v*td.w;
            }
            float* dst = g_dvec + ((size_t)(b*8 + hs)*16 + cg*4)*64;
            dst[0*64 + j] = d0;
            dst[1*64 + j] = d1;
            dst[2*64 + j] = d2;
            dst[3*64 + j] = d3;
        }
    }

    batch_barrier(&g_cntB[b*32], tid);

    // ---------------- phase C: balanced rows, sync-free ---------------------
    {
        float sb = score_b[0];
        const float* dvA = g_dvec + (size_t)(b*8 + hsA)*1024;
        const float* dvB = g_dvec + (size_t)(b*8 + hsB)*1024;
        for (int v = tid; v < 1024; v += 256) {
            ush[v] = __ldcg(dvA + v);
            tsm[v] = __ldcg(dvB + v);
        }
        if (tid < 16) {
            bshC[tid]      = 0.125f*__ldcg(g_s + b*128 + hsA*16 + tid) + sb;
            bshC[16 + tid] = 0.125f*__ldcg(g_s + b*128 + hsB*16 + tid) + sb;
        }
        __syncthreads();

        int lane = tid & 31, warp = tid >> 5;
        int half = lane >> 4, j = lane & 15;
        int p0 = warp*2 + half;                  // 0..15
        int p3 = p0 + 48;
        bool v3 = (p3 < WW);

        #pragma unroll
        for (int r = 0; r < 4; r++) {
            int h = start + r;
            if (h >= end) break;
            bool isA = ((int)c_hseg[h] == hsA);
            const float* dsm = isA ? ush : tsm;
            const float* bs  = bshC + (isA ? 0 : 16);
            int gibase = (b*HH + h)*WW;

            // result-holding lanes prefetch noise (latency overlaps dot)
            float nx0=0,nx1=0,nx2=0,nx3=0, nr0=0,nr1=0,nr2=0,nr3=0;
            if (j == 0) {
                nx0 = noise_x[gibase + p0];
                nx1 = noise_x[gibase + p0 + 16];
                nx2 = noise_x[gibase + p0 + 32];
                nr0 = noise_r[gibase + p0];
                nr1 = noise_r[gibase + p0 + 16];
                nr2 = noise_r[gibase + p0 + 32];
                if (v3) { nx3 = noise_x[gibase + p3]; nr3 = noise_r[gibase + p3]; }
            }

            const float4* xr4 = (const float4*)(x + (size_t)gibase * DD);
            float4 a0 = xr4[(p0      )*16 + j];
            float4 a1 = xr4[(p0 + 16)*16 + j];
            float4 a2 = xr4[(p0 + 32)*16 + j];
            float4 a3 = v3 ? xr4[p3*16 + j] : make_float4(0.f,0.f,0.f,0.f);

            int ws0 = c_wseg[p0], ws1 = c_wseg[p0+16], ws2 = c_wseg[p0+32];
            int ws3 = v3 ? (int)c_wseg[p3] : 0;
            float4 d0 = ((const float4*)(dsm + ws0*64))[j];
            float4 d1 = ((const float4*)(dsm + ws1*64))[j];
            float4 d2 = ((const float4*)(dsm + ws2*64))[j];
            float4 d3 = ((const float4*)(dsm + ws3*64))[j];

            float t0 = a0.x*d0.x + a0.y*d0.y + a0.z*d0.z + a0.w*d0.w;
            float t1 = a1.x*d1.x + a1.y*d1.y + a1.z*d1.z + a1.w*d1.w;
            float t2 = a2.x*d2.x + a2.y*d2.y + a2.z*d2.z + a2.w*d2.w;
            float t3 = a3.x*d3.x + a3.y*d3.y + a3.z*d3.z + a3.w*d3.w;

            #pragma unroll
            for (int o = 1; o < 16; o <<= 1) {
                t0 += __shfl_xor_sync(0xffffffffu, t0, o);
                t1 += __shfl_xor_sync(0xffffffffu, t1, o);
                t2 += __shfl_xor_sync(0xffffffffu, t2, o);
                t3 += __shfl_xor_sync(0xffffffffu, t3, o);
            }
            if (j == 0) {
                out[gibase + p0]      = gumbel_mask(0.125f*t0 + bs[ws0], nx0, nr0);
                out[gibase + p0 + 16] = gumbel_mask(0.125f*t1 + bs[ws1], nx1, nr1);
                out[gibase + p0 + 32] = gumbel_mask(0.125f*t2 + bs[ws2], nx2, nr2);
                if (v3) out[gibase + p3] = gumbel_mask(0.125f*t3 + bs[ws3], nx3, nr3);
            }
        }
    }
}

// ---------------- launcher ----------------
extern "C" void kernel_launch(void* const* d_in, const int* in_sizes, int n_in,
                              void* d_out, int out_size) {
    const float* x       = (const float*)d_in[0];   // (64,30,60,64)
    const float* qk_w    = (const float*)d_in[1];   // (128,64)
    const float* qk_b    = (const float*)d_in[2];   // (128,)
    const float* score_w = (const float*)d_in[3];   // (1,3)
    const float* score_b = (const float*)d_in[4];   // (1,)
    const float* noise_x = (const float*)d_in[5];   // (64,1800,1)
    const float* noise_r = (const float*)d_in[6];   // (64,1800,1)
    float* out = (float*)d_out;                     // (64,1800,1)

    k_fused<<<NB*8, 256>>>(x, qk_w, qk_b, score_w, score_b, noise_x, noise_r, out);
}

// round 9
// speedup vs baseline: 1.2796x; 1.2796x over previous
#include <cuda_runtime.h>
#include <math.h>

#define NB 64
#define HH 30
#define WW 60
#define DD 64

// ---------------- scratch (device globals; no allocation) ----------------
__device__ float g_part[NB*16*16*DD];     // balanced partial cell sums (4 MB)
__device__ float g_dvec[NB*128*DD];       // d vectors [b][combo][e] (2 MB)
__device__ float g_s[NB*128];             // s (incl. wsum*cb)
__device__ float g_Mt[DD*DD];             // (Wq^T Wk) transposed: Mt[f][e]
__device__ float g_v1[DD];                // Wq^T bk
__device__ float g_v2[DD];                // Wk^T bq
__device__ float g_cb;                    // bq . bk

// ---------------- geometry LUTs ----------------
__constant__ int c_wstart[16] = {0,6,10,12,15,18,20,24,30,36,40,42,45,48,50,54};
__constant__ int c_wlen[16]   = {6,4,2,3,3,2,4,6, 6,4,2,3,3,2,4,6};
__constant__ unsigned char c_hseg[30] = {
  0,0,0,0,0,0, 1,1,1,1, 2,2, 3,3,3, 4,4,4, 5,5, 6,6,6,6, 7,7,7,7,7,7};
__constant__ unsigned char c_wseg[60] = {
  0,0,0,0,0,0, 1,1,1,1, 2,2, 3,3,3, 4,4,4, 5,5, 6,6,6,6, 7,7,7,7,7,7,
  8,8,8,8,8,8, 9,9,9,9, 10,10, 11,11,11, 12,12,12, 13,13, 14,14,14,14,
  15,15,15,15,15,15};
// forward maps seg -> pool region index
__constant__ unsigned char c_rh0[8]  = {0,1,1,2,2,3,3,4};
__constant__ unsigned char c_rh1[8]  = {0,0,1,1,1,1,2,2};
__constant__ unsigned char c_rh2[8]  = {0,0,0,0,1,1,1,1};
__constant__ unsigned char c_rw0[16] = {0,1,1,2,2,3,3,4,5,6,6,7,7,8,8,9};
__constant__ unsigned char c_rw1[16] = {0,0,1,1,1,1,2,2,3,3,4,4,4,4,5,5};
__constant__ unsigned char c_rw2[16] = {0,0,0,0,1,1,1,1,2,2,2,2,3,3,3,3};
// inverse maps: region row/col -> [first seg, count]
__constant__ unsigned char p0_hf[5]={0,1,3,5,7},              p0_hc[5]={1,2,2,2,1};
__constant__ unsigned char p0_wf[10]={0,1,3,5,7,8,9,11,13,15},p0_wc[10]={1,2,2,2,1,1,2,2,2,1};
__constant__ unsigned char p1_hf[3]={0,2,6},                  p1_hc[3]={2,4,2};
__constant__ unsigned char p1_wf[6]={0,2,6,8,10,14},          p1_wc[6]={2,4,2,2,4,2};
__constant__ unsigned char p2_hf[2]={0,4},                    p2_hc[2]={4,4};
__constant__ unsigned char p2_wf[4]={0,4,8,12},               p2_wc[4]={4,4,4,4};
// hseg -> the two g_part slots that sum to its cells (slots 1,9,15 are zeros)
__constant__ unsigned char c_i1[8] = {0,3,5,7,8,10,11,13};
__constant__ unsigned char c_i2[8] = {2,4,6,1,9,15,12,14};

// ---------------- kernel A: balanced partial cell sums + fused prep --------
// blocks [0,512): (batch, k): contiguous row range sizes 3,4,4,4,3,4,4,4;
// each range spans <=2 hsegs -> two partial slots. blocks [512,528): prep.
__global__ __launch_bounds__(256) void k_cells(const float* __restrict__ x,
                                               const float* __restrict__ qk_w,
                                               const float* __restrict__ qk_b) {
    int bi = blockIdx.x;
    int tid = threadIdx.x;
    if (bi >= 512) {
        int t = (bi - 512) * 256 + tid;
        int e = t & 63, f = t >> 6;
        float s = 0.f;
        #pragma unroll 8
        for (int d = 0; d < 64; d++)
            s += qk_w[d*64 + e] * qk_w[(64 + d)*64 + f];
        g_Mt[f*64 + e] = s;
        if (bi == 512) {
            if (tid < 64) {
                float a = 0.f;
                for (int d = 0; d < 64; d++) a += qk_w[d*64 + tid] * qk_b[64 + d];
                g_v1[tid] = a;
            } else if (tid < 128) {
                int ff = tid - 64; float a = 0.f;
                for (int d = 0; d < 64; d++) a += qk_w[(64 + d)*64 + ff] * qk_b[d];
                g_v2[ff] = a;
            } else if (tid == 128) {
                float a = 0.f;
                for (int d = 0; d < 64; d++) a += qk_b[d] * qk_b[64 + d];
                g_cb = a;
            }
        }
        return;
    }
    int b = bi >> 3, k = bi & 7;
    int start = (k*30) >> 3, end = ((k+1)*30) >> 3;
    int hsA = c_hseg[start];
    int ws = tid >> 4, j = tid & 15;
    int a0 = c_wstart[ws], l0 = c_wlen[ws];
    const float4* xb4 = (const float4*)(x + (size_t)(b*HH) * WW * DD);
    float4 accA = make_float4(0.f,0.f,0.f,0.f);
    float4 accB = make_float4(0.f,0.f,0.f,0.f);
    #pragma unroll
    for (int r = 0; r < 4; r++) {
        int h = start + r;
        if (h < end) {
            const float4* xr = xb4 + (h*WW + a0)*16 + j;
            float4 t = make_float4(0.f,0.f,0.f,0.f);
            #pragma unroll
            for (int w = 0; w < 6; w++) {
                if (w < l0) {
                    float4 v = xr[w*16];
                    t.x += v.x; t.y += v.y; t.z += v.z; t.w += v.w;
                }
            }
            if ((int)c_hseg[h] == hsA) {
                accA.x += t.x; accA.y += t.y; accA.z += t.z; accA.w += t.w;
            } else {
                accB.x += t.x; accB.y += t.y; accB.z += t.z; accB.w += t.w;
            }
        }
    }
    float4* pp = (float4*)(g_part + ((size_t)b*16 + k*2) * 1024);
    pp[ws*16 + j]       = accA;
    pp[256 + ws*16 + j] = accB;
}

// ---------------- kernel B: fused regions + matvec (reads g_part) ---------
__global__ __launch_bounds__(256) void k_mid(const float* __restrict__ score_w) {
    __shared__ float rs[20*64];                    // 5 KB
    __shared__ __align__(16) float ush[16*64];     // 4 KB
    __shared__ float Msh[4096];                    // 16 KB
    int b = blockIdx.x >> 3, hs = blockIdx.x & 7;
    int tid = threadIdx.x;

    for (int v = tid; v < 4096; v += 256) Msh[v] = g_Mt[v];

    const float* pb = g_part + (size_t)b * 16384;
    int rh0 = c_rh0[hs], rh1 = c_rh1[hs], rh2 = c_rh2[hs];
    for (int v = tid; v < 1280; v += 256) {
        int jj = v >> 6, d = v & 63;
        int hf, hc, wf, wc;
        if (jj < 10)      { hf=p0_hf[rh0]; hc=p0_hc[rh0]; wf=p0_wf[jj];   wc=p0_wc[jj]; }
        else if (jj < 16) { int rw=jj-10; hf=p1_hf[rh1]; hc=p1_hc[rh1]; wf=p1_wf[rw]; wc=p1_wc[rw]; }
        else              { int rw=jj-16; hf=p2_hf[rh2]; hc=p2_hc[rh2]; wf=p2_wf[rw]; wc=p2_wc[rw]; }
        float s = 0.f;
        for (int a = 0; a < hc; a++) {
            int hsr = hf + a;
            const float* q1 = pb + (int)c_i1[hsr]*1024;
            const float* q2 = pb + (int)c_i2[hsr]*1024;
            for (int c2 = 0; c2 < wc; c2++) {
                int o = (wf + c2)*64 + d;
                s += q1[o] + q2[o];
            }
        }
        rs[v] = s;
    }
    __syncthreads();

    float w0 = score_w[0], w1 = score_w[1], w2 = score_w[2];
    float a0 = w0*(1.f/36.f), a1 = w1*(1.f/100.f), a2 = w2*(1.f/225.f);
    float wsum = w0 + w1 + w2;

    for (int v = tid; v < 1024; v += 256) {
        int ws = v >> 6, f = v & 63;
        ush[v] = a0*rs[(int)c_rw0[ws]*64 + f]
               + a1*rs[(10 + (int)c_rw1[ws])*64 + f]
               + a2*rs[(16 + (int)c_rw2[ws])*64 + f];
    }
    __syncthreads();

    // s[c] = v2 . u[c] + wsum*cb
    int lane = tid & 31, warp = tid >> 5;
    for (int ws = warp; ws < 16; ws += 8) {
        float sv = ush[ws*64 + lane]      * g_v2[lane]
                 + ush[ws*64 + 32 + lane] * g_v2[32 + lane];
        #pragma unroll
        for (int o = 16; o; o >>= 1) sv += __shfl_xor_sync(0xffffffffu, sv, o);
        if (lane == 0) g_s[b*128 + hs*16 + ws] = sv + wsum * g_cb;
    }

    // matvec: d[c] = Mt^T u[c] + wsum*v1
    int e = tid & 63, cg = tid >> 6;
    float init = wsum * g_v1[e];
    float acc0 = init, acc1 = init, acc2 = init, acc3 = init;
    const float4* u0 = (const float4*)(ush + (cg*4 + 0)*64);
    const float4* u1 = (const float4*)(ush + (cg*4 + 1)*64);
    const float4* u2 = (const float4*)(ush + (cg*4 + 2)*64);
    const float4* u3 = (const float4*)(ush + (cg*4 + 3)*64);
    #pragma unroll
    for (int fq = 0; fq < 16; fq++) {
        int f = fq*4;
        float m0 = Msh[(f+0)*64 + e];
        float m1 = Msh[(f+1)*64 + e];
        float m2 = Msh[(f+2)*64 + e];
        float m3 = Msh[(f+3)*64 + e];
        float4 a = u0[fq], bb = u1[fq], c = u2[fq], dd = u3[fq];
        acc0 += m0*a.x  + m1*a.y  + m2*a.z  + m3*a.w;
        acc1 += m0*bb.x + m1*bb.y + m2*bb.z + m3*bb.w;
        acc2 += m0*c.x  + m1*c.y  + m2*c.z  + m3*c.w;
        acc3 += m0*dd.x + m1*dd.y + m2*dd.z + m3*dd.w;
    }
    float* dst = g_dvec + ((size_t)(b*128 + hs*16 + cg*4))*64;
    dst[0*64 + e] = acc0;
    dst[1*64 + e] = acc1;
    dst[2*64 + e] = acc2;
    dst[3*64 + e] = acc3;
}

// ---------------- kernel C: quad-per-pixel dot + reduced-MUFU gumbel -------
// block = one image row; 4 lanes per pixel (64B contiguous each); 2 shfl/px;
// logit identity removes sigmoid+2log: mask = sigmoid((attn + nx - nr)/T).
__global__ __launch_bounds__(256) void k_final(const float* __restrict__ x,
                                               const float* __restrict__ score_b,
                                               const float* __restrict__ noise_x,
                                               const float* __restrict__ noise_r,
                                               float* __restrict__ out) {
    __shared__ __align__(16) float dsh[1024];
    __shared__ float bsh[16];                 // 0.125*s + score_b
    int bh = blockIdx.x;
    int b = bh / HH, h = bh - b*HH;
    int hs = c_hseg[h];
    int tid = threadIdx.x;

    int lane = tid & 31, warp = tid >> 5;
    int px = warp*8 + (lane >> 2);            // 0..63
    int q  = lane & 3;
    bool valid = (px < WW);
    int gi = bh*WW + px;

    // early noise loads (only output lanes) -> latency overlaps everything
    float nxv = 0.f, nrv = 0.f;
    if (valid && q == 0) { nxv = noise_x[gi]; nrv = noise_r[gi]; }

    const float* dsrc = g_dvec + ((size_t)(b*128 + hs*16))*64;
    for (int v = tid; v < 1024; v += 256) dsh[v] = dsrc[v];
    if (tid < 16) bsh[tid] = 0.125f * g_s[b*128 + hs*16 + tid] + score_b[0];
    __syncthreads();

    float dot = 0.f;
    int ws = 0;
    if (valid) {
        ws = c_wseg[px];
        const float4* xp = (const float4*)(x + (size_t)bh * WW * DD) + px*16 + q*4;
        const float4* dp = ((const float4*)dsh) + ws*16 + q*4;
        float4 x0 = xp[0], x1 = xp[1], x2 = xp[2], x3 = xp[3];
        float4 d0 = dp[0], d1 = dp[1], d2 = dp[2], d3 = dp[3];
        dot  = x0.x*d0.x + x0.y*d0.y + x0.z*d0.z + x0.w*d0.w;
        dot += x1.x*d1.x + x1.y*d1.y + x1.z*d1.z + x1.w*d1.w;
        dot += x2.x*d2.x + x2.y*d2.y + x2.z*d2.z + x2.w*d2.w;
        dot += x3.x*d3.x + x3.y*d3.y + x3.z*d3.z + x3.w*d3.w;
    }
    dot += __shfl_xor_sync(0xffffffffu, dot, 1);
    dot += __shfl_xor_sync(0xffffffffu, dot, 2);

    if (valid && q == 0) {
        float attn = 0.125f*dot + bsh[ws];
        // log(sig+eps) - log(1-sig+eps) == attn  (|attn| < ~10 here; err ~1e-6)
        float nx = -logf(-logf(nxv + 1e-8f) + 1e-8f);
        float nr = -logf(-logf(nrv + 1e-8f) + 1e-8f);
        const float invT = 1.f / (0.03f + 1e-8f);
        float l = (attn + nx - nr) * invT;
        out[gi] = 1.f / (1.f + expf(-l));
    }
}

// ---------------- launcher ----------------
extern "C" void kernel_launch(void* const* d_in, const int* in_sizes, int n_in,
                              void* d_out, int out_size) {
    const float* x       = (const float*)d_in[0];   // (64,30,60,64)
    const float* qk_w    = (const float*)d_in[1];   // (128,64)
    const float* qk_b    = (const float*)d_in[2];   // (128,)
    const float* score_w = (const float*)d_in[3];   // (1,3)
    const float* score_b = (const float*)d_in[4];   // (1,)
    const float* noise_x = (const float*)d_in[5];   // (64,1800,1)
    const float* noise_r = (const float*)d_in[6];   // (64,1800,1)
    float* out = (float*)d_out;                     // (64,1800,1)

    k_cells<<<528,   256>>>(x, qk_w, qk_b);
    k_mid  <<<NB*8,  256>>>(score_w);
    k_final<<<NB*HH, 256>>>(x, score_b, noise_x, noise_r, out);
}

// round 10
// speedup vs baseline: 1.6594x; 1.2968x over previous
#include <cuda_runtime.h>
#include <math.h>

#define NB 64
#define HH 30
#define WW 60
#define DD 64
#define ROWB (WW*DD*4)      // 15360 bytes per (b,h) image row

// ---------------- scratch (device globals; no allocation) ----------------
__device__ float g_cell[NB*8*16*DD];      // hseg-cell sums of x   (2 MB)
__device__ float g_dvec[NB*128*DD];       // d vectors [b][combo][e] (2 MB)
__device__ float g_s[NB*128];
__device__ float g_Mt[DD*DD];             // (Wq^T Wk) transposed: Mt[f][e]
__device__ float g_v1[DD];                // Wq^T bk
__device__ float g_v2[DD];                // Wk^T bq
__device__ float g_cb;                    // bq . bk

// ---------------- geometry LUTs ----------------
__constant__ int c_hstart[8] = {0,6,10,12,15,18,20,24};
__constant__ int c_hlen[8]   = {6,4,2,3,3,2,4,6};
__constant__ int c_wstart[16] = {0,6,10,12,15,18,20,24,30,36,40,42,45,48,50,54};
__constant__ int c_wlen[16]   = {6,4,2,3,3,2,4,6, 6,4,2,3,3,2,4,6};
__constant__ unsigned char c_hseg[30] = {
  0,0,0,0,0,0, 1,1,1,1, 2,2, 3,3,3, 4,4,4, 5,5, 6,6,6,6, 7,7,7,7,7,7};
__constant__ unsigned char c_wseg[60] = {
  0,0,0,0,0,0, 1,1,1,1, 2,2, 3,3,3, 4,4,4, 5,5, 6,6,6,6, 7,7,7,7,7,7,
  8,8,8,8,8,8, 9,9,9,9, 10,10, 11,11,11, 12,12,12, 13,13, 14,14,14,14,
  15,15,15,15,15,15};
// forward maps seg -> pool region index
__constant__ unsigned char c_rh0[8]  = {0,1,1,2,2,3,3,4};
__constant__ unsigned char c_rh1[8]  = {0,0,1,1,1,1,2,2};
__constant__ unsigned char c_rh2[8]  = {0,0,0,0,1,1,1,1};
__constant__ unsigned char c_rw0[16] = {0,1,1,2,2,3,3,4,5,6,6,7,7,8,8,9};
__constant__ unsigned char c_rw1[16] = {0,0,1,1,1,1,2,2,3,3,4,4,4,4,5,5};
__constant__ unsigned char c_rw2[16] = {0,0,0,0,1,1,1,1,2,2,2,2,3,3,3,3};
// inverse maps: region row/col -> [first seg, count]
__constant__ unsigned char p0_hf[5]={0,1,3,5,7},              p0_hc[5]={1,2,2,2,1};
__constant__ unsigned char p0_wf[10]={0,1,3,5,7,8,9,11,13,15},p0_wc[10]={1,2,2,2,1,1,2,2,2,1};
__constant__ unsigned char p1_hf[3]={0,2,6},                  p1_hc[3]={2,4,2};
__constant__ unsigned char p1_wf[6]={0,2,6,8,10,14},          p1_wc[6]={2,4,2,2,4,2};
__constant__ unsigned char p2_hf[2]={0,4},                    p2_hc[2]={4,4};
__constant__ unsigned char p2_wf[4]={0,4,8,12},               p2_wc[4]={4,4,4,4};

// ---------------- bulk-async helpers ----------------
__device__ __forceinline__ unsigned s2u(const void* p) {
    unsigned a;
    asm("{ .reg .u64 t; cvta.to.shared.u64 t, %1; cvt.u32.u64 %0, t; }"
        : "=r"(a) : "l"(p));
    return a;
}
__device__ __forceinline__ void mbar_init(unsigned m, unsigned cnt) {
    asm volatile("mbarrier.init.shared.b64 [%0], %1;" :: "r"(m), "r"(cnt) : "memory");
}
__device__ __forceinline__ void mbar_expect(unsigned m, unsigned bytes) {
    asm volatile("mbarrier.arrive.expect_tx.shared.b64 _, [%0], %1;"
                 :: "r"(m), "r"(bytes) : "memory");
}
__device__ __forceinline__ void bulk_g2s(unsigned dst, const void* src,
                                         unsigned bytes, unsigned m) {
    asm volatile(
        "cp.async.bulk.shared::cluster.global.mbarrier::complete_tx::bytes "
        "[%0], [%1], %2, [%3];"
        :: "r"(dst), "l"(src), "r"(bytes), "r"(m) : "memory");
}
__device__ __forceinline__ void mbar_wait(unsigned m, unsigned parity) {
    asm volatile(
        "{\n\t.reg .pred P;\n\t"
        "WL_%=:\n\t"
        "mbarrier.try_wait.parity.acquire.cta.shared::cta.b64 P, [%0], %1;\n\t"
        "@P bra WD_%=;\n\t"
        "bra WL_%=;\n\t"
        "WD_%=:\n\t}"
        :: "r"(m), "r"(parity) : "memory");
}

// ---------------- kernel A: bulk-async cell sums + fused prep --------------
// blocks [0,512): (batch, hseg). 3-slot row ring via cp.async.bulk; consume
// from smem with conflict-free 16-lane float4 pattern; register accumulate.
// blocks [512,528): weight precompute (Mt, v1, v2, cb).
__global__ __launch_bounds__(256) void k_cells(const float* __restrict__ x,
                                               const float* __restrict__ qk_w,
                                               const float* __restrict__ qk_b) {
    __shared__ __align__(128) float4 slab[3][WW*16];       // 3 x 15360 B
    __shared__ __align__(8) unsigned long long mbar[3];
    int bi = blockIdx.x;
    int tid = threadIdx.x;
    if (bi >= 512) {
        int t = (bi - 512) * 256 + tid;
        int e = t & 63, f = t >> 6;
        float s = 0.f;
        #pragma unroll 8
        for (int d = 0; d < 64; d++)
            s += qk_w[d*64 + e] * qk_w[(64 + d)*64 + f];
        g_Mt[f*64 + e] = s;
        if (bi == 512) {
            if (tid < 64) {
                float a = 0.f;
                for (int d = 0; d < 64; d++) a += qk_w[d*64 + tid] * qk_b[64 + d];
                g_v1[tid] = a;
            } else if (tid < 128) {
                int ff = tid - 64; float a = 0.f;
                for (int d = 0; d < 64; d++) a += qk_w[(64 + d)*64 + ff] * qk_b[d];
                g_v2[ff] = a;
            } else if (tid == 128) {
                float a = 0.f;
                for (int d = 0; d < 64; d++) a += qk_b[d] * qk_b[64 + d];
                g_cb = a;
            }
        }
        return;
    }
    int b = bi >> 3, hs = bi & 7;
    int h0 = c_hstart[hs], hl = c_hlen[hs];
    int ws = tid >> 4, j = tid & 15;
    int a0 = c_wstart[ws], l0 = c_wlen[ws];

    unsigned mb0 = s2u(&mbar[0]);
    if (tid == 0) {
        mbar_init(mb0,      1);
        mbar_init(mb0 + 8,  1);
        mbar_init(mb0 + 16, 1);
    }
    __syncthreads();

    const char* xrow = (const char*)x + (size_t)(b*HH + h0) * ROWB;
    if (tid == 0) {
        int pre = hl < 3 ? hl : 3;
        for (int r = 0; r < pre; r++) {
            mbar_expect(mb0 + r*8, ROWB);
            bulk_g2s(s2u(&slab[r][0]), xrow + (size_t)r*ROWB, ROWB, mb0 + r*8);
        }
    }

    float4 acc = make_float4(0.f, 0.f, 0.f, 0.f);
    for (int r = 0; r < hl; r++) {
        int s = r % 3;                       // hl<=6: each slot reused <=2x
        mbar_wait(mb0 + s*8, r/3);
        const float4* sl = &slab[s][a0*16 + j];
        #pragma unroll
        for (int w = 0; w < 6; w++) {
            if (w < l0) {
                float4 v = sl[w*16];
                acc.x += v.x; acc.y += v.y; acc.z += v.z; acc.w += v.w;
            }
        }
        __syncthreads();                     // slot free for reuse
        if (tid == 0 && r + 3 < hl) {
            asm volatile("fence.proxy.async.shared::cta;" ::: "memory");
            mbar_expect(mb0 + s*8, ROWB);
            bulk_g2s(s2u(&slab[s][0]), xrow + (size_t)(r+3)*ROWB, ROWB, mb0 + s*8);
        }
    }
    ((float4*)(g_cell + (size_t)(b*8 + hs) * 1024))[ws*16 + j] = acc;
}

// ---------------- kernel B: fused regions + matvec (R6, proven) ------------
__global__ __launch_bounds__(256) void k_mid(const float* __restrict__ score_w) {
    __shared__ float rs[20*64];
    __shared__ __align__(16) float ush[16*64];
    __shared__ float Msh[4096];
    int b = blockIdx.x >> 3, hs = blockIdx.x & 7;
    int tid = threadIdx.x;

    for (int v = tid; v < 4096; v += 256) Msh[v] = g_Mt[v];

    const float* cbp = g_cell + (size_t)b * 8192;
    int rh0 = c_rh0[hs], rh1 = c_rh1[hs], rh2 = c_rh2[hs];
    for (int v = tid; v < 1280; v += 256) {
        int jj = v >> 6, d = v & 63;
        int hf, hc, wf, wc;
        if (jj < 10)      { hf=p0_hf[rh0]; hc=p0_hc[rh0]; wf=p0_wf[jj];   wc=p0_wc[jj]; }
        else if (jj < 16) { int rw=jj-10; hf=p1_hf[rh1]; hc=p1_hc[rh1]; wf=p1_wf[rw]; wc=p1_wc[rw]; }
        else              { int rw=jj-16; hf=p2_hf[rh2]; hc=p2_hc[rh2]; wf=p2_wf[rw]; wc=p2_wc[rw]; }
        float s = 0.f;
        for (int a = 0; a < hc; a++)
            for (int c2 = 0; c2 < wc; c2++)
                s += cbp[(hf + a)*1024 + (wf + c2)*64 + d];
        rs[v] = s;
    }
    __syncthreads();

    float w0 = score_w[0], w1 = score_w[1], w2 = score_w[2];
    float a0 = w0*(1.f/36.f), a1 = w1*(1.f/100.f), a2 = w2*(1.f/225.f);
    float wsum = w0 + w1 + w2;

    for (int v = tid; v < 1024; v += 256) {
        int ws = v >> 6, f = v & 63;
        ush[v] = a0*rs[(int)c_rw0[ws]*64 + f]
               + a1*rs[(10 + (int)c_rw1[ws])*64 + f]
               + a2*rs[(16 + (int)c_rw2[ws])*64 + f];
    }
    __syncthreads();

    int lane = tid & 31, warp = tid >> 5;
    for (int ws = warp; ws < 16; ws += 8) {
        float sv = ush[ws*64 + lane]      * g_v2[lane]
                 + ush[ws*64 + 32 + lane] * g_v2[32 + lane];
        #pragma unroll
        for (int o = 16; o; o >>= 1) sv += __shfl_xor_sync(0xffffffffu, sv, o);
        if (lane == 0) g_s[b*128 + hs*16 + ws] = sv + wsum * g_cb;
    }

    int e = tid & 63, cg = tid >> 6;
    float init = wsum * g_v1[e];
    float acc0 = init, acc1 = init, acc2 = init, acc3 = init;
    const float4* u0 = (const float4*)(ush + (cg*4 + 0)*64);
    const float4* u1 = (const float4*)(ush + (cg*4 + 1)*64);
    const float4* u2 = (const float4*)(ush + (cg*4 + 2)*64);
    const float4* u3 = (const float4*)(ush + (cg*4 + 3)*64);
    #pragma unroll
    for (int fq = 0; fq < 16; fq++) {
        int f = fq*4;
        float m0 = Msh[(f+0)*64 + e];
        float m1 = Msh[(f+1)*64 + e];
        float m2 = Msh[(f+2)*64 + e];
        float m3 = Msh[(f+3)*64 + e];
        float4 a = u0[fq], bb = u1[fq], c = u2[fq], dd = u3[fq];
        acc0 += m0*a.x  + m1*a.y  + m2*a.z  + m3*a.w;
        acc1 += m0*bb.x + m1*bb.y + m2*bb.z + m3*bb.w;
        acc2 += m0*c.x  + m1*c.y  + m2*c.z  + m3*c.w;
        acc3 += m0*dd.x + m1*dd.y + m2*dd.z + m3*dd.w;
    }
    float* dst = g_dvec + ((size_t)(b*128 + hs*16 + cg*4))*64;
    dst[0*64 + e] = acc0;
    dst[1*64 + e] = acc1;
    dst[2*64 + e] = acc2;
    dst[3*64 + e] = acc3;
}

// ---------------- kernel C: bulk-async row + 16-lane dot + logit gumbel ----
__global__ __launch_bounds__(256) void k_final(const float* __restrict__ x,
                                               const float* __restrict__ score_b,
                                               const float* __restrict__ noise_x,
                                               const float* __restrict__ noise_r,
                                               float* __restrict__ out) {
    __shared__ __align__(128) float4 xs[WW*16];            // 15360 B
    __shared__ __align__(16) float dsh[1024];
    __shared__ float bsh[16];
    __shared__ float ash[64];
    __shared__ __align__(8) unsigned long long mbar;
    int bh = blockIdx.x;
    int b = bh / HH, h = bh - b*HH;
    int hs = c_hseg[h];
    int tid = threadIdx.x;

    unsigned mb = s2u(&mbar);
    if (tid == 0) mbar_init(mb, 1);
    __syncthreads();
    if (tid == 0) {
        mbar_expect(mb, ROWB);
        bulk_g2s(s2u(xs), (const char*)x + (size_t)bh * ROWB, ROWB, mb);
    }

    // overlap the bulk copy with noise / dvec / s staging
    int gi = bh * WW + tid;
    float nxv = 0.f, nrv = 0.f;
    if (tid < WW) { nxv = noise_x[gi]; nrv = noise_r[gi]; }
    const float* dsrc = g_dvec + ((size_t)(b*128 + hs*16))*64;
    for (int v = tid; v < 1024; v += 256) dsh[v] = dsrc[v];
    if (tid < 16) bsh[tid] = 0.125f * g_s[b*128 + hs*16 + tid] + score_b[0];
    __syncthreads();
    mbar_wait(mb, 0);

    int lane = tid & 31, warp = tid >> 5;
    int half = lane >> 4, j = lane & 15;
    int p0 = warp*2 + half;                  // 0..15
    #pragma unroll
    for (int it = 0; it < 4; it++) {
        int p = p0 + it*16;
        float dot = 0.f; int wsg = 0;
        if (p < WW) {
            wsg = c_wseg[p];
            float4 a = xs[p*16 + j];                         // 256B/half-warp, conflict-free
            float4 d = ((const float4*)dsh)[wsg*16 + j];
            dot = a.x*d.x + a.y*d.y + a.z*d.z + a.w*d.w;
        }
        #pragma unroll
        for (int o = 1; o < 16; o <<= 1) dot += __shfl_xor_sync(0xffffffffu, dot, o);
        if (p < WW && j == 0) ash[p] = 0.125f*dot + bsh[wsg];
    }
    __syncthreads();

    if (tid < WW) {
        float attn = ash[tid];
        // log(sig+eps) - log(1-sig+eps) == attn  (|attn| small; err ~1e-6)
        float nx = -logf(-logf(nxv + 1e-8f) + 1e-8f);
        float nr = -logf(-logf(nrv + 1e-8f) + 1e-8f);
        const float invT = 1.f / (0.03f + 1e-8f);
        float l = (attn + nx - nr) * invT;
        out[gi] = 1.f / (1.f + expf(-l));
    }
}

// ---------------- launcher ----------------
extern "C" void kernel_launch(void* const* d_in, const int* in_sizes, int n_in,
                              void* d_out, int out_size) {
    const float* x       = (const float*)d_in[0];   // (64,30,60,64)
    const float* qk_w    = (const float*)d_in[1];   // (128,64)
    const float* qk_b    = (const float*)d_in[2];   // (128,)
    const float* score_w = (const float*)d_in[3];   // (1,3)
    const float* score_b = (const float*)d_in[4];   // (1,)
    const float* noise_x = (const float*)d_in[5];   // (64,1800,1)
    const float* noise_r = (const float*)d_in[6];   // (64,1800,1)
    float* out = (float*)d_out;                     // (64,1800,1)

    k_cells<<<528,   256>>>(x, qk_w, qk_b);
    k_mid  <<<NB*8,  256>>>(score_w);
    k_final<<<NB*HH, 256>>>(x, score_b, noise_x, noise_r, out);
}

// round 11
// speedup vs baseline: 1.6609x; 1.0010x over previous
#include <cuda_runtime.h>
#include <math.h>

#define NB 64
#define HH 30
#define WW 60
#define DD 64
#define ROWB (WW*DD*4)      // 15360 bytes per (b,h) image row

// ---------------- scratch (device globals; no allocation) ----------------
__device__ float g_cell[NB*8*16*DD];      // hseg-cell sums of x   (2 MB)
__device__ float g_dvec[NB*128*DD];       // d vectors [b][combo][e] (2 MB)
__device__ float g_s[NB*128];
__device__ float g_Mt[DD*DD];             // (Wq^T Wk) transposed: Mt[f][e]
__device__ float g_v1[DD];                // Wq^T bk
__device__ float g_v2[DD];                // Wk^T bq
__device__ float g_cb;                    // bq . bk

// ---------------- geometry LUTs ----------------
__constant__ int c_hstart[8] = {0,6,10,12,15,18,20,24};
__constant__ int c_hlen[8]   = {6,4,2,3,3,2,4,6};
__constant__ int c_wstart[16] = {0,6,10,12,15,18,20,24,30,36,40,42,45,48,50,54};
__constant__ int c_wlen[16]   = {6,4,2,3,3,2,4,6, 6,4,2,3,3,2,4,6};
__constant__ unsigned char c_hseg[30] = {
  0,0,0,0,0,0, 1,1,1,1, 2,2, 3,3,3, 4,4,4, 5,5, 6,6,6,6, 7,7,7,7,7,7};
__constant__ unsigned char c_wseg[60] = {
  0,0,0,0,0,0, 1,1,1,1, 2,2, 3,3,3, 4,4,4, 5,5, 6,6,6,6, 7,7,7,7,7,7,
  8,8,8,8,8,8, 9,9,9,9, 10,10, 11,11,11, 12,12,12, 13,13, 14,14,14,14,
  15,15,15,15,15,15};
// forward maps seg -> pool region index
__constant__ unsigned char c_rh0[8]  = {0,1,1,2,2,3,3,4};
__constant__ unsigned char c_rh1[8]  = {0,0,1,1,1,1,2,2};
__constant__ unsigned char c_rh2[8]  = {0,0,0,0,1,1,1,1};
__constant__ unsigned char c_rw0[16] = {0,1,1,2,2,3,3,4,5,6,6,7,7,8,8,9};
__constant__ unsigned char c_rw1[16] = {0,0,1,1,1,1,2,2,3,3,4,4,4,4,5,5};
__constant__ unsigned char c_rw2[16] = {0,0,0,0,1,1,1,1,2,2,2,2,3,3,3,3};
// inverse maps: region row/col -> [first seg, count]
__constant__ unsigned char p0_hf[5]={0,1,3,5,7},              p0_hc[5]={1,2,2,2,1};
__constant__ unsigned char p0_wf[10]={0,1,3,5,7,8,9,11,13,15},p0_wc[10]={1,2,2,2,1,1,2,2,2,1};
__constant__ unsigned char p1_hf[3]={0,2,6},                  p1_hc[3]={2,4,2};
__constant__ unsigned char p1_wf[6]={0,2,6,8,10,14},          p1_wc[6]={2,4,2,2,4,2};
__constant__ unsigned char p2_hf[2]={0,4},                    p2_hc[2]={4,4};
__constant__ unsigned char p2_wf[4]={0,4,8,12},               p2_wc[4]={4,4,4,4};

// ---------------- bulk-async + PDL helpers ----------------
__device__ __forceinline__ unsigned s2u(const void* p) {
    unsigned a;
    asm("{ .reg .u64 t; cvta.to.shared.u64 t, %1; cvt.u32.u64 %0, t; }"
        : "=r"(a) : "l"(p));
    return a;
}
__device__ __forceinline__ void mbar_init(unsigned m, unsigned cnt) {
    asm volatile("mbarrier.init.shared.b64 [%0], %1;" :: "r"(m), "r"(cnt) : "memory");
}
__device__ __forceinline__ void mbar_expect(unsigned m, unsigned bytes) {
    asm volatile("mbarrier.arrive.expect_tx.shared.b64 _, [%0], %1;"
                 :: "r"(m), "r"(bytes) : "memory");
}
__device__ __forceinline__ void bulk_g2s(unsigned dst, const void* src,
                                         unsigned bytes, unsigned m) {
    asm volatile(
        "cp.async.bulk.shared::cluster.global.mbarrier::complete_tx::bytes "
        "[%0], [%1], %2, [%3];"
        :: "r"(dst), "l"(src), "r"(bytes), "r"(m) : "memory");
}
__device__ __forceinline__ void mbar_wait(unsigned m, unsigned parity) {
    asm volatile(
        "{\n\t.reg .pred P;\n\t"
        "WL_%=:\n\t"
        "mbarrier.try_wait.parity.acquire.cta.shared::cta.b64 P, [%0], %1;\n\t"
        "@P bra WD_%=;\n\t"
        "bra WL_%=;\n\t"
        "WD_%=:\n\t}"
        :: "r"(m), "r"(parity) : "memory");
}
__device__ __forceinline__ void gdc_wait() {
    asm volatile("griddepcontrol.wait;" ::: "memory");
}
__device__ __forceinline__ void gdc_launch() {
    asm volatile("griddepcontrol.launch_dependents;" ::: "memory");
}

// ---------------- kernel A: bulk-async cell sums + fused prep --------------
__global__ __launch_bounds__(256) void k_cells(const float* __restrict__ x,
                                               const float* __restrict__ qk_w,
                                               const float* __restrict__ qk_b) {
    __shared__ __align__(128) float4 slab[3][WW*16];       // 3 x 15360 B
    __shared__ __align__(8) unsigned long long mbar[3];
    int bi = blockIdx.x;
    int tid = threadIdx.x;
    if (bi >= 512) {
        int t = (bi - 512) * 256 + tid;
        int e = t & 63, f = t >> 6;
        float s = 0.f;
        #pragma unroll 8
        for (int d = 0; d < 64; d++)
            s += qk_w[d*64 + e] * qk_w[(64 + d)*64 + f];
        g_Mt[f*64 + e] = s;
        if (bi == 512) {
            if (tid < 64) {
                float a = 0.f;
                for (int d = 0; d < 64; d++) a += qk_w[d*64 + tid] * qk_b[64 + d];
                g_v1[tid] = a;
            } else if (tid < 128) {
                int ff = tid - 64; float a = 0.f;
                for (int d = 0; d < 64; d++) a += qk_w[(64 + d)*64 + ff] * qk_b[d];
                g_v2[ff] = a;
            } else if (tid == 128) {
                float a = 0.f;
                for (int d = 0; d < 64; d++) a += qk_b[d] * qk_b[64 + d];
                g_cb = a;
            }
        }
        gdc_launch();
        return;
    }
    int b = bi >> 3, hs = bi & 7;
    int h0 = c_hstart[hs], hl = c_hlen[hs];
    int ws = tid >> 4, j = tid & 15;
    int a0 = c_wstart[ws], l0 = c_wlen[ws];

    unsigned mb0 = s2u(&mbar[0]);
    if (tid == 0) {
        mbar_init(mb0,      1);
        mbar_init(mb0 + 8,  1);
        mbar_init(mb0 + 16, 1);
    }
    __syncthreads();

    const char* xrow = (const char*)x + (size_t)(b*HH + h0) * ROWB;
    if (tid == 0) {
        int pre = hl < 3 ? hl : 3;
        for (int r = 0; r < pre; r++) {
            mbar_expect(mb0 + r*8, ROWB);
            bulk_g2s(s2u(&slab[r][0]), xrow + (size_t)r*ROWB, ROWB, mb0 + r*8);
        }
    }

    float4 acc = make_float4(0.f, 0.f, 0.f, 0.f);
    for (int r = 0; r < hl; r++) {
        int s = r % 3;                       // hl<=6: each slot reused <=2x
        mbar_wait(mb0 + s*8, r/3);
        const float4* sl = &slab[s][a0*16 + j];
        #pragma unroll
        for (int w = 0; w < 6; w++) {
            if (w < l0) {
                float4 v = sl[w*16];
                acc.x += v.x; acc.y += v.y; acc.z += v.z; acc.w += v.w;
            }
        }
        __syncthreads();                     // slot free for reuse
        if (tid == 0 && r + 3 < hl) {
            asm volatile("fence.proxy.async.shared::cta;" ::: "memory");
            mbar_expect(mb0 + s*8, ROWB);
            bulk_g2s(s2u(&slab[s][0]), xrow + (size_t)(r+3)*ROWB, ROWB, mb0 + s*8);
        }
    }
    ((float4*)(g_cell + (size_t)(b*8 + hs) * 1024))[ws*16 + j] = acc;
    gdc_launch();                            // last dependent store done
}

// ---------------- kernel B: fused regions + matvec (PDL dependent) ---------
__global__ __launch_bounds__(256) void k_mid(const float* __restrict__ score_w) {
    __shared__ float rs[20*64];
    __shared__ __align__(16) float ush[16*64];
    __shared__ float Msh[4096];
    int b = blockIdx.x >> 3, hs = blockIdx.x & 7;
    int tid = threadIdx.x;

    float w0 = score_w[0], w1 = score_w[1], w2 = score_w[2];   // inputs: pre-wait
    gdc_wait();                              // g_Mt / g_cell ready past here

    for (int v = tid; v < 4096; v += 256) Msh[v] = g_Mt[v];

    const float* cbp = g_cell + (size_t)b * 8192;
    int rh0 = c_rh0[hs], rh1 = c_rh1[hs], rh2 = c_rh2[hs];
    for (int v = tid; v < 1280; v += 256) {
        int jj = v >> 6, d = v & 63;
        int hf, hc, wf, wc;
        if (jj < 10)      { hf=p0_hf[rh0]; hc=p0_hc[rh0]; wf=p0_wf[jj];   wc=p0_wc[jj]; }
        else if (jj < 16) { int rw=jj-10; hf=p1_hf[rh1]; hc=p1_hc[rh1]; wf=p1_wf[rw]; wc=p1_wc[rw]; }
        else              { int rw=jj-16; hf=p2_hf[rh2]; hc=p2_hc[rh2]; wf=p2_wf[rw]; wc=p2_wc[rw]; }
        float s = 0.f;
        for (int a = 0; a < hc; a++)
            for (int c2 = 0; c2 < wc; c2++)
                s += cbp[(hf + a)*1024 + (wf + c2)*64 + d];
        rs[v] = s;
    }
    __syncthreads();

    float a0 = w0*(1.f/36.f), a1 = w1*(1.f/100.f), a2 = w2*(1.f/225.f);
    float wsum = w0 + w1 + w2;

    for (int v = tid; v < 1024; v += 256) {
        int ws = v >> 6, f = v & 63;
        ush[v] = a0*rs[(int)c_rw0[ws]*64 + f]
               + a1*rs[(10 + (int)c_rw1[ws])*64 + f]
               + a2*rs[(16 + (int)c_rw2[ws])*64 + f];
    }
    __syncthreads();

    int lane = tid & 31, warp = tid >> 5;
    for (int ws = warp; ws < 16; ws += 8) {
        float sv = ush[ws*64 + lane]      * g_v2[lane]
                 + ush[ws*64 + 32 + lane] * g_v2[32 + lane];
        #pragma unroll
        for (int o = 16; o; o >>= 1) sv += __shfl_xor_sync(0xffffffffu, sv, o);
        if (lane == 0) g_s[b*128 + hs*16 + ws] = sv + wsum * g_cb;
    }

    int e = tid & 63, cg = tid >> 6;
    float init = wsum * g_v1[e];
    float acc0 = init, acc1 = init, acc2 = init, acc3 = init;
    const float4* u0 = (const float4*)(ush + (cg*4 + 0)*64);
    const float4* u1 = (const float4*)(ush + (cg*4 + 1)*64);
    const float4* u2 = (const float4*)(ush + (cg*4 + 2)*64);
    const float4* u3 = (const float4*)(ush + (cg*4 + 3)*64);
    #pragma unroll
    for (int fq = 0; fq < 16; fq++) {
        int f = fq*4;
        float m0 = Msh[(f+0)*64 + e];
        float m1 = Msh[(f+1)*64 + e];
        float m2 = Msh[(f+2)*64 + e];
        float m3 = Msh[(f+3)*64 + e];
        float4 a = u0[fq], bb = u1[fq], c = u2[fq], dd = u3[fq];
        acc0 += m0*a.x  + m1*a.y  + m2*a.z  + m3*a.w;
        acc1 += m0*bb.x + m1*bb.y + m2*bb.z + m3*bb.w;
        acc2 += m0*c.x  + m1*c.y  + m2*c.z  + m3*c.w;
        acc3 += m0*dd.x + m1*dd.y + m2*dd.z + m3*dd.w;
    }
    float* dst = g_dvec + ((size_t)(b*128 + hs*16 + cg*4))*64;
    dst[0*64 + e] = acc0;
    dst[1*64 + e] = acc1;
    dst[2*64 + e] = acc2;
    dst[3*64 + e] = acc3;
    gdc_launch();                            // dvec/s stored
}

// ---------------- kernel C: PDL dependent; x/noise prefetch pre-wait -------
__global__ __launch_bounds__(256) void k_final(const float* __restrict__ x,
                                               const float* __restrict__ score_b,
                                               const float* __restrict__ noise_x,
                                               const float* __restrict__ noise_r,
                                               float* __restrict__ out) {
    __shared__ __align__(128) float4 xs[WW*16];            // 15360 B
    __shared__ __align__(16) float dsh[1024];
    __shared__ float bsh[16];
    __shared__ float ash[64];
    __shared__ __align__(8) unsigned long long mbar;
    int bh = blockIdx.x;
    int b = bh / HH, h = bh - b*HH;
    int hs = c_hseg[h];
    int tid = threadIdx.x;

    // ---- pre-wait: inputs only (x, noise, score_b) ----
    unsigned mb = s2u(&mbar);
    if (tid == 0) mbar_init(mb, 1);
    __syncthreads();
    if (tid == 0) {
        mbar_expect(mb, ROWB);
        bulk_g2s(s2u(xs), (const char*)x + (size_t)bh * ROWB, ROWB, mb);
    }
    int gi = bh * WW + tid;
    float nxv = 0.f, nrv = 0.f;
    if (tid < WW) { nxv = noise_x[gi]; nrv = noise_r[gi]; }
    float sb = score_b[0];

    gdc_wait();                              // g_dvec / g_s ready past here

    const float* dsrc = g_dvec + ((size_t)(b*128 + hs*16))*64;
    for (int v = tid; v < 1024; v += 256) dsh[v] = dsrc[v];
    if (tid < 16) bsh[tid] = 0.125f * g_s[b*128 + hs*16 + tid] + sb;
    __syncthreads();
    mbar_wait(mb, 0);

    int lane = tid & 31, warp = tid >> 5;
    int half = lane >> 4, j = lane & 15;
    int p0 = warp*2 + half;                  // 0..15
    #pragma unroll
    for (int it = 0; it < 4; it++) {
        int p = p0 + it*16;
        float dot = 0.f; int wsg = 0;
        if (p < WW) {
            wsg = c_wseg[p];
            float4 a = xs[p*16 + j];
            float4 d = ((const float4*)dsh)[wsg*16 + j];
            dot = a.x*d.x + a.y*d.y + a.z*d.z + a.w*d.w;
        }
        #pragma unroll
        for (int o = 1; o < 16; o <<= 1) dot += __shfl_xor_sync(0xffffffffu, dot, o);
        if (p < WW && j == 0) ash[p] = 0.125f*dot + bsh[wsg];
    }
    __syncthreads();

    if (tid < WW) {
        float attn = ash[tid];
        // log(sig+eps) - log(1-sig+eps) == attn  (|attn| small; err ~1e-6)
        float nx = -logf(-logf(nxv + 1e-8f) + 1e-8f);
        float nr = -logf(-logf(nrv + 1e-8f) + 1e-8f);
        const float invT = 1.f / (0.03f + 1e-8f);
        float l = (attn + nx - nr) * invT;
        out[gi] = 1.f / (1.f + expf(-l));
    }
}

// ---------------- launcher (PDL on both dependent kernels) ----------------
extern "C" void kernel_launch(void* const* d_in, const int* in_sizes, int n_in,
                              void* d_out, int out_size) {
    const float* x       = (const float*)d_in[0];   // (64,30,60,64)
    const float* qk_w    = (const float*)d_in[1];   // (128,64)
    const float* qk_b    = (const float*)d_in[2];   // (128,)
    const float* score_w = (const float*)d_in[3];   // (1,3)
    const float* score_b = (const float*)d_in[4];   // (1,)
    const float* noise_x = (const float*)d_in[5];   // (64,1800,1)
    const float* noise_r = (const float*)d_in[6];   // (64,1800,1)
    float* out = (float*)d_out;                     // (64,1800,1)

    k_cells<<<528, 256>>>(x, qk_w, qk_b);

    cudaLaunchAttribute at[1];
    at[0].id = cudaLaunchAttributeProgrammaticStreamSerialization;
    at[0].val.programmaticStreamSerializationAllowed = 1;

    {
        cudaLaunchConfig_t cfg = {};
        cfg.gridDim = dim3(NB*8);
        cfg.blockDim = dim3(256);
        cfg.dynamicSmemBytes = 0;
        cfg.stream = 0;
        cfg.attrs = at; cfg.numAttrs = 1;
        void* args[] = { (void*)&score_w };
        cudaLaunchKernelExC(&cfg, (const void*)k_mid, args);
    }
    {
        cudaLaunchConfig_t cfg = {};
        cfg.gridDim = dim3(NB*HH);
        cfg.blockDim = dim3(256);
        cfg.dynamicSmemBytes = 0;
        cfg.stream = 0;
        cfg.attrs = at; cfg.numAttrs = 1;
        void* args[] = { (void*)&x, (void*)&score_b, (void*)&noise_x,
                         (void*)&noise_r, (void*)&out };
        cudaLaunchKernelExC(&cfg, (const void*)k_final, args);
    }
}

// round 12
// speedup vs baseline: 1.7818x; 1.0727x over previous
#include <cuda_runtime.h>
#include <math.h>

#define NB 64
#define HH 30
#define WW 60
#define DD 64
#define ROWB (WW*DD*4)      // 15360 bytes per (b,h) image row

// ---------------- scratch (device globals; no allocation) ----------------
__device__ float g_part[NB*16*16*DD];     // balanced partial cell sums (4 MB)
__device__ float g_dvec[NB*8*16*DD];      // dvec per (batch,hseg,combo) (2 MB)
__device__ float g_s[NB*128];             // raw s
__device__ unsigned g_cntA[NB*32];        // barrier counters (monotonic, replay-safe)
__device__ unsigned g_cntB[NB*32];

// ---------------- geometry LUTs ----------------
__constant__ int c_wstart[16] = {0,6,10,12,15,18,20,24,30,36,40,42,45,48,50,54};
__constant__ int c_wlen[16]   = {6,4,2,3,3,2,4,6, 6,4,2,3,3,2,4,6};
__constant__ unsigned char c_hseg[30] = {
  0,0,0,0,0,0, 1,1,1,1, 2,2, 3,3,3, 4,4,4, 5,5, 6,6,6,6, 7,7,7,7,7,7};
__constant__ unsigned char c_wseg[60] = {
  0,0,0,0,0,0, 1,1,1,1, 2,2, 3,3,3, 4,4,4, 5,5, 6,6,6,6, 7,7,7,7,7,7,
  8,8,8,8,8,8, 9,9,9,9, 10,10, 11,11,11, 12,12,12, 13,13, 14,14,14,14,
  15,15,15,15,15,15};
__constant__ unsigned char c_rh0[8]  = {0,1,1,2,2,3,3,4};
__constant__ unsigned char c_rh1[8]  = {0,0,1,1,1,1,2,2};
__constant__ unsigned char c_rh2[8]  = {0,0,0,0,1,1,1,1};
__constant__ unsigned char c_rw0[16] = {0,1,1,2,2,3,3,4,5,6,6,7,7,8,8,9};
__constant__ unsigned char c_rw1[16] = {0,0,1,1,1,1,2,2,3,3,4,4,4,4,5,5};
__constant__ unsigned char c_rw2[16] = {0,0,0,0,1,1,1,1,2,2,2,2,3,3,3,3};
__constant__ unsigned char p0_hf[5]={0,1,3,5,7},              p0_hc[5]={1,2,2,2,1};
__constant__ unsigned char p0_wf[10]={0,1,3,5,7,8,9,11,13,15},p0_wc[10]={1,2,2,2,1,1,2,2,2,1};
__constant__ unsigned char p1_hf[3]={0,2,6},                  p1_hc[3]={2,4,2};
__constant__ unsigned char p1_wf[6]={0,2,6,8,10,14},          p1_wc[6]={2,4,2,2,4,2};
__constant__ unsigned char p2_hf[2]={0,4},                    p2_hc[2]={4,4};
__constant__ unsigned char p2_wf[4]={0,4,8,12},               p2_wc[4]={4,4,4,4};
// hseg -> two g_part slots summing to its cells (slots 1,9,15 are zeros)
__constant__ unsigned char c_i1[8] = {0,3,5,7,8,10,11,13};
__constant__ unsigned char c_i2[8] = {2,4,6,1,9,15,12,14};

// ---------------- async / barrier helpers ----------------
__device__ __forceinline__ unsigned s2u(const void* p) {
    unsigned a;
    asm("{ .reg .u64 t; cvta.to.shared.u64 t, %1; cvt.u32.u64 %0, t; }"
        : "=r"(a) : "l"(p));
    return a;
}
__device__ __forceinline__ void mbar_init(unsigned m, unsigned cnt) {
    asm volatile("mbarrier.init.shared.b64 [%0], %1;" :: "r"(m), "r"(cnt) : "memory");
}
__device__ __forceinline__ void mbar_expect(unsigned m, unsigned bytes) {
    asm volatile("mbarrier.arrive.expect_tx.shared.b64 _, [%0], %1;"
                 :: "r"(m), "r"(bytes) : "memory");
}
__device__ __forceinline__ void bulk_g2s(unsigned dst, const void* src,
                                         unsigned bytes, unsigned m) {
    asm volatile(
        "cp.async.bulk.shared::cluster.global.mbarrier::complete_tx::bytes "
        "[%0], [%1], %2, [%3];"
        :: "r"(dst), "l"(src), "r"(bytes), "r"(m) : "memory");
}
__device__ __forceinline__ void mbar_wait(unsigned m, unsigned parity) {
    asm volatile(
        "{\n\t.reg .pred P;\n\t"
        "WL_%=:\n\t"
        "mbarrier.try_wait.parity.acquire.cta.shared::cta.b64 P, [%0], %1;\n\t"
        "@P bra WD_%=;\n\t"
        "bra WL_%=;\n\t"
        "WD_%=:\n\t}"
        :: "r"(m), "r"(parity) : "memory");
}
__device__ __forceinline__ void fence_async() {
    asm volatile("fence.proxy.async.shared::cta;" ::: "memory");
}
__device__ __forceinline__ void batch_barrier(unsigned* cnt, int tid) {
    __threadfence();                         // release this block's stores
    __syncthreads();
    if (tid == 0) {
        unsigned o = atomicAdd(cnt, 1u);
        unsigned target = ((o >> 3) + 1u) << 3;   // next multiple of 8
        while ((int)(*(volatile unsigned*)cnt - target) < 0) __nanosleep(128);
        __threadfence();                     // acquire
    }
    __syncthreads();
}

// ============ fused kernel: grid = 512 = (batch, k), one wave ============
__global__ __launch_bounds__(256, 4) void k_fused(
    const float* __restrict__ x,
    const float* __restrict__ qk_w,
    const float* __restrict__ qk_b,
    const float* __restrict__ score_w,
    const float* __restrict__ score_b,
    const float* __restrict__ noise_x,
    const float* __restrict__ noise_r,
    float* __restrict__ out)
{
    // arena layout (byte offsets):
    //  A: slabs 0/1/2 at 0/15360/30720                       (46080)
    //  B: Msh 0..16640 (64x65 pad), rs4 @16640, ush4 @21760, tsm @25856
    //  C: slabs 0/1 at 0/15360, dshA @30720, dshB @34816, ash @38912, bsh @39936
    __shared__ __align__(128) unsigned char arena[46080];
    __shared__ __align__(8) unsigned long long mbar[5];
    __shared__ float qkb[128];

    int bi  = blockIdx.x;
    int b   = bi >> 3, k = bi & 7;
    int tid = threadIdx.x;
    int start = (k*30) >> 3, end = ((k+1)*30) >> 3;   // sizes 3,4,4,4,3,4,4,4
    int rows  = end - start;
    int hsA = c_hseg[start], hsB = c_hseg[end - 1];   // range spans <= 2 hsegs

    unsigned mb = s2u(mbar);
    if (tid == 0)
        for (int i = 0; i < 5; i++) mbar_init(mb + i*8, 1);
    if (tid < 128) qkb[tid] = qk_b[tid];
    float w0 = score_w[0], w1 = score_w[1], w2 = score_w[2];
    float sb = score_b[0];
    // noise preload (input-only): overlaps all phases
    int gi0 = (b*HH + start)*WW;
    float nxv = 0.f, nrv = 0.f;
    if (tid < rows*WW) { nxv = noise_x[gi0 + tid]; nrv = noise_r[gi0 + tid]; }
    __syncthreads();

    const char* xrow = (const char*)x + (size_t)(b*HH + start) * ROWB;

    // ---------------- phase A: balanced TMA cell partials -------------------
    {
        if (tid == 0) {
            int pre = rows < 3 ? rows : 3;
            for (int r = 0; r < pre; r++) {
                mbar_expect(mb + r*8, ROWB);
                bulk_g2s(s2u(arena + r*15360), xrow + (size_t)r*ROWB, ROWB, mb + r*8);
            }
        }
        int ws = tid >> 4, j = tid & 15;
        int a0i = c_wstart[ws], l0 = c_wlen[ws];
        float4 accA = make_float4(0.f,0.f,0.f,0.f);
        float4 accB = make_float4(0.f,0.f,0.f,0.f);
        #pragma unroll
        for (int r = 0; r < 4; r++) {
            if (r < rows) {
                int s = r % 3;
                mbar_wait(mb + s*8, r/3);
                const float4* sl = (const float4*)(arena + s*15360) + a0i*16 + j;
                float4 t = make_float4(0.f,0.f,0.f,0.f);
                #pragma unroll
                for (int w = 0; w < 6; w++) {
                    if (w < l0) {
                        float4 v = sl[w*16];
                        t.x += v.x; t.y += v.y; t.z += v.z; t.w += v.w;
                    }
                }
                if ((int)c_hseg[start + r] == hsA) {
                    accA.x += t.x; accA.y += t.y; accA.z += t.z; accA.w += t.w;
                } else {
                    accB.x += t.x; accB.y += t.y; accB.z += t.z; accB.w += t.w;
                }
                __syncthreads();             // slab free for reuse
                if (tid == 0 && r + 3 < rows) {
                    fence_async();
                    mbar_expect(mb + s*8, ROWB);
                    bulk_g2s(s2u(arena + s*15360), xrow + (size_t)(r+3)*ROWB,
                             ROWB, mb + s*8);
                }
            }
        }
        float4* pp = (float4*)(g_part + ((size_t)b*16 + k*2) * 1024);
        pp[ws*16 + j]       = accA;          // slot k*2
        pp[256 + ws*16 + j] = accB;          // slot k*2+1 (zeros if single-hseg)
    }

    batch_barrier(&g_cntA[b*32], tid);

    // ---------------- phase B: regions(f4) -> u -> t -> (s, dvec) -----------
    {
        float*  Msh  = (float*)arena;                    // 64x65 padded
        float4* rs4  = (float4*)(arena + 16640);         // 20 regions x 16 f4
        float4* ush4 = (float4*)(arena + 21760);         // 16 combos x 16 f4
        float*  tsm  = (float*)(arena + 25856);          // 16 x 64

        // Wk transposed, bank-padded: Msh[d*65+e] = Wk[e][d]
        for (int v = tid; v < 4096; v += 256) {
            int e = v >> 6, d = v & 63;
            Msh[d*65 + e] = qk_w[4096 + v];
        }

        // region sums (float4 gather over two partial slots per cell row)
        const float4* pb4 = (const float4*)(g_part + (size_t)b * 16384);
        int rh0 = c_rh0[k], rh1 = c_rh1[k], rh2 = c_rh2[k];
        for (int v = tid; v < 320; v += 256) {
            int jj = v >> 4, dq = v & 15;
            int hf, hc, wf, wc;
            if (jj < 10)      { hf=p0_hf[rh0]; hc=p0_hc[rh0]; wf=p0_wf[jj];   wc=p0_wc[jj]; }
            else if (jj < 16) { int rw=jj-10; hf=p1_hf[rh1]; hc=p1_hc[rh1]; wf=p1_wf[rw]; wc=p1_wc[rw]; }
            else              { int rw=jj-16; hf=p2_hf[rh2]; hc=p2_hc[rh2]; wf=p2_wf[rw]; wc=p2_wc[rw]; }
            float4 s = make_float4(0.f,0.f,0.f,0.f);
            for (int a = 0; a < hc; a++) {
                int hsr = hf + a;
                const float4* q1 = pb4 + (int)c_i1[hsr]*256;
                const float4* q2 = pb4 + (int)c_i2[hsr]*256;
                for (int c2 = 0; c2 < wc; c2++) {
                    int o = (wf + c2)*16 + dq;
                    float4 v1 = q1[o], v2 = q2[o];
                    s.x += v1.x + v2.x; s.y += v1.y + v2.y;
                    s.z += v1.z + v2.z; s.w += v1.w + v2.w;
                }
            }
            rs4[v] = s;
        }
        __syncthreads();

        float aw0 = w0*(1.f/36.f), aw1 = w1*(1.f/100.f), aw2 = w2*(1.f/225.f);
        float wsum = w0 + w1 + w2;

        // u[combo] (256 threads = 16 combos x 16 quads, exactly one each)
        {
            int wsg = tid >> 4, dq = tid & 15;
            float4 r0 = rs4[(int)c_rw0[wsg]*16 + dq];
            float4 r1 = rs4[(10 + (int)c_rw1[wsg])*16 + dq];
            float4 r2 = rs4[(16 + (int)c_rw2[wsg])*16 + dq];
            float4 u;
            u.x = aw0*r0.x + aw1*r1.x + aw2*r2.x;
            u.y = aw0*r0.y + aw1*r1.y + aw2*r2.y;
            u.z = aw0*r0.z + aw1*r1.z + aw2*r2.z;
            u.w = aw0*r0.w + aw1*r1.w + aw2*r2.w;
            ush4[tid] = u;
        }
        __syncthreads();

        // t[c] = Wk u[c] + wsum*bk   (thread = (e, 4-combo group))
        int e = tid & 63, cg = tid >> 6;
        {
            float init = wsum * qkb[64 + e];
            float t0 = init, t1 = init, t2 = init, t3 = init;
            #pragma unroll
            for (int fq = 0; fq < 16; fq++) {
                int d = fq*4;
                float m0 = Msh[(d+0)*65 + e];
                float m1 = Msh[(d+1)*65 + e];
                float m2 = Msh[(d+2)*65 + e];
                float m3 = Msh[(d+3)*65 + e];
                float4 ua = ush4[(cg*4 + 0)*16 + fq];
                float4 ub = ush4[(cg*4 + 1)*16 + fq];
                float4 uc = ush4[(cg*4 + 2)*16 + fq];
                float4 ud = ush4[(cg*4 + 3)*16 + fq];
                t0 += m0*ua.x + m1*ua.y + m2*ua.z + m3*ua.w;
                t1 += m0*ub.x + m1*ub.y + m2*ub.z + m3*ub.w;
                t2 += m0*uc.x + m1*uc.y + m2*uc.z + m3*uc.w;
                t3 += m0*ud.x + m1*ud.y + m2*ud.z + m3*ud.w;
            }
            tsm[(cg*4 + 0)*64 + e] = t0;
            tsm[(cg*4 + 1)*64 + e] = t1;
            tsm[(cg*4 + 2)*64 + e] = t2;
            tsm[(cg*4 + 3)*64 + e] = t3;
        }
        __syncthreads();

        // reload Msh with Wq (straight layout)
        for (int v = tid; v < 4096; v += 256) Msh[v] = qk_w[v];
        __syncthreads();

        // s[c] = bq . t[c]
        int lane = tid & 31, warp = tid >> 5;
        for (int c = warp; c < 16; c += 8) {
            float sv = tsm[c*64 + lane]      * qkb[lane]
                     + tsm[c*64 + 32 + lane] * qkb[32 + lane];
            #pragma unroll
            for (int o = 16; o; o >>= 1) sv += __shfl_xor_sync(0xffffffffu, sv, o);
            if (lane == 0) g_s[b*128 + k*16 + c] = sv;
        }

        // dvec[c] = Wq^T t[c] -> global
        {
            int jj = tid & 63;
            float d0 = 0.f, d1 = 0.f, d2 = 0.f, d3 = 0.f;
            const float4* t0p = (const float4*)(tsm + (cg*4 + 0)*64);
            const float4* t1p = (const float4*)(tsm + (cg*4 + 1)*64);
            const float4* t2p = (const float4*)(tsm + (cg*4 + 2)*64);
            const float4* t3p = (const float4*)(tsm + (cg*4 + 3)*64);
            #pragma unroll
            for (int eq = 0; eq < 16; eq++) {
                int ee = eq*4;
                float a0v = Msh[(ee+0)*64 + jj];
                float a1v = Msh[(ee+1)*64 + jj];
                float a2v = Msh[(ee+2)*64 + jj];
                float a3v = Msh[(ee+3)*64 + jj];
                float4 ta = t0p[eq], tb = t1p[eq], tc = t2p[eq], td = t3p[eq];
                d0 += a0v*ta.x + a1v*ta.y + a2v*ta.z + a3v*ta.w;
                d1 += a0v*tb.x + a1v*tb.y + a2v*tb.z + a3v*tb.w;
                d2 += a0v*tc.x + a1v*tc.y + a2v*tc.z + a3v*tc.w;
                d3 += a0v*td.x + a1v*td.y + a2v*td.z + a3v*td.w;
            }
            float* dst = g_dvec + ((size_t)(b*8 + k)*16 + cg*4)*64;
            dst[0*64 + jj] = d0;
            dst[1*64 + jj] = d1;
            dst[2*64 + jj] = d2;
            dst[3*64 + jj] = d3;
        }
    }

    batch_barrier(&g_cntB[b*32], tid);

    // ---------------- phase C: TMA rows from L2 + dot + gumbel --------------
    {
        float4* dshA4 = (float4*)(arena + 30720);
        float4* dshB4 = (float4*)(arena + 34816);
        float*  ashp  = (float*)(arena + 38912);
        float*  bshA  = (float*)(arena + 39936);
        float*  bshB  = bshA + 16;

        if (tid == 0) {
            fence_async();
            mbar_expect(mb + 24, ROWB);
            bulk_g2s(s2u(arena), xrow, ROWB, mb + 24);
            if (rows > 1) {
                mbar_expect(mb + 32, ROWB);
                bulk_g2s(s2u(arena + 15360), xrow + (size_t)ROWB, ROWB, mb + 32);
            }
        }
        const float4* srcA = (const float4*)(g_dvec + (size_t)(b*8 + hsA)*1024);
        const float4* srcB = (const float4*)(g_dvec + (size_t)(b*8 + hsB)*1024);
        dshA4[tid] = srcA[tid];              // 256 f4 = full 16x64 each
        dshB4[tid] = srcB[tid];
        if (tid < 16) {
            bshA[tid] = 0.125f * g_s[b*128 + hsA*16 + tid] + sb;
            bshB[tid] = 0.125f * g_s[b*128 + hsB*16 + tid] + sb;
        }
        __syncthreads();

        int lane = tid & 31, warp = tid >> 5;
        int half = lane >> 4, jq = lane & 15;
        int p0 = warp*2 + half;              // 0..15
        for (int r = 0; r < rows; r++) {
            int buf = r & 1;
            mbar_wait(mb + 24 + buf*8, r >> 1);
            const float4* xs4 = (const float4*)(arena + buf*15360);
            bool isA = ((int)c_hseg[start + r] == hsA);
            const float4* dsm = isA ? dshA4 : dshB4;
            const float*  bs  = isA ? bshA  : bshB;
            #pragma unroll
            for (int it = 0; it < 4; it++) {
                int p = p0 + it*16;
                float dot = 0.f; int wsg = 0;
                if (p < WW) {
                    wsg = c_wseg[p];
                    float4 a = xs4[p*16 + jq];
                    float4 d = dsm[wsg*16 + jq];
                    dot = a.x*d.x + a.y*d.y + a.z*d.z + a.w*d.w;
                }
                #pragma unroll
                for (int o = 1; o < 16; o <<= 1)
                    dot += __shfl_xor_sync(0xffffffffu, dot, o);
                if (p < WW && jq == 0) ashp[r*WW + p] = 0.125f*dot + bs[wsg];
            }
            __syncthreads();                 // buffer free + ash visible
            if (tid == 0 && r + 2 < rows) {
                fence_async();
                mbar_expect(mb + 24 + buf*8, ROWB);
                bulk_g2s(s2u(arena + buf*15360), xrow + (size_t)(r+2)*ROWB,
                         ROWB, mb + 24 + buf*8);
            }
        }

        if (tid < rows*WW) {
            float attn = ashp[tid];
            // log(sig+eps) - log(1-sig+eps) == attn  (|attn| small; err ~1e-6)
            float nx = -logf(-logf(nxv + 1e-8f) + 1e-8f);
            float nr = -logf(-logf(nrv + 1e-8f) + 1e-8f);
            const float invT = 1.f / (0.03f + 1e-8f);
            float l = (attn + nx - nr) * invT;
            out[gi0 + tid] = 1.f / (1.f + expf(-l));
        }
    }
}

// ---------------- launcher ----------------
extern "C" void kernel_launch(void* const* d_in, const int* in_sizes, int n_in,
                              void* d_out, int out_size) {
    const float* x       = (const float*)d_in[0];   // (64,30,60,64)
    const float* qk_w    = (const float*)d_in[1];   // (128,64)
    const float* qk_b    = (const float*)d_in[2];   // (128,)
    const float* score_w = (const float*)d_in[3];   // (1,3)
    const float* score_b = (const float*)d_in[4];   // (1,)
    const float* noise_x = (const float*)d_in[5];   // (64,1800,1)
    const float* noise_r = (const float*)d_in[6];   // (64,1800,1)
    float* out = (float*)d_out;                     // (64,1800,1)

    k_fused<<<NB*8, 256>>>(x, qk_w, qk_b, score_w, score_b,
                           noise_x, noise_r, out);
}

// round 13
// speedup vs baseline: 1.7946x; 1.0072x over previous
#include <cuda_runtime.h>
#include <math.h>

#define NB 64
#define HH 30
#define WW 60
#define DD 64
#define ROWB (WW*DD*4)      // 15360 bytes per (b,h) image row

// ---------------- scratch (device globals; no allocation) ----------------
__device__ float g_part[NB*16*16*DD];     // balanced partial cell sums (4 MB)
__device__ float g_dvec[NB*8*16*DD];      // dvec per (batch,hseg,combo) (2 MB)
__device__ float g_s[NB*128];             // raw s
__device__ unsigned g_cntA[NB*32];        // barrier counters (monotonic, replay-safe)
__device__ unsigned g_cntB[NB*32];

// ---------------- geometry LUTs ----------------
__constant__ int c_wstart[16] = {0,6,10,12,15,18,20,24,30,36,40,42,45,48,50,54};
__constant__ int c_wlen[16]   = {6,4,2,3,3,2,4,6, 6,4,2,3,3,2,4,6};
__constant__ unsigned char c_hseg[30] = {
  0,0,0,0,0,0, 1,1,1,1, 2,2, 3,3,3, 4,4,4, 5,5, 6,6,6,6, 7,7,7,7,7,7};
__constant__ unsigned char c_wseg[60] = {
  0,0,0,0,0,0, 1,1,1,1, 2,2, 3,3,3, 4,4,4, 5,5, 6,6,6,6, 7,7,7,7,7,7,
  8,8,8,8,8,8, 9,9,9,9, 10,10, 11,11,11, 12,12,12, 13,13, 14,14,14,14,
  15,15,15,15,15,15};
__constant__ unsigned char c_rh0[8]  = {0,1,1,2,2,3,3,4};
__constant__ unsigned char c_rh1[8]  = {0,0,1,1,1,1,2,2};
__constant__ unsigned char c_rh2[8]  = {0,0,0,0,1,1,1,1};
__constant__ unsigned char c_rw0[16] = {0,1,1,2,2,3,3,4,5,6,6,7,7,8,8,9};
__constant__ unsigned char c_rw1[16] = {0,0,1,1,1,1,2,2,3,3,4,4,4,4,5,5};
__constant__ unsigned char c_rw2[16] = {0,0,0,0,1,1,1,1,2,2,2,2,3,3,3,3};
__constant__ unsigned char p0_hf[5]={0,1,3,5,7},              p0_hc[5]={1,2,2,2,1};
__constant__ unsigned char p0_wf[10]={0,1,3,5,7,8,9,11,13,15},p0_wc[10]={1,2,2,2,1,1,2,2,2,1};
__constant__ unsigned char p1_hf[3]={0,2,6},                  p1_hc[3]={2,4,2};
__constant__ unsigned char p1_wf[6]={0,2,6,8,10,14},          p1_wc[6]={2,4,2,2,4,2};
__constant__ unsigned char p2_hf[2]={0,4},                    p2_hc[2]={4,4};
__constant__ unsigned char p2_wf[4]={0,4,8,12},               p2_wc[4]={4,4,4,4};
// hseg -> two g_part slots summing to its cells (slots 1,9,15 are zeros)
__constant__ unsigned char c_i1[8] = {0,3,5,7,8,10,11,13};
__constant__ unsigned char c_i2[8] = {2,4,6,1,9,15,12,14};

// ---------------- async / barrier helpers ----------------
__device__ __forceinline__ unsigned s2u(const void* p) {
    unsigned a;
    asm("{ .reg .u64 t; cvta.to.shared.u64 t, %1; cvt.u32.u64 %0, t; }"
        : "=r"(a) : "l"(p));
    return a;
}
__device__ __forceinline__ void mbar_init(unsigned m, unsigned cnt) {
    asm volatile("mbarrier.init.shared.b64 [%0], %1;" :: "r"(m), "r"(cnt) : "memory");
}
__device__ __forceinline__ void mbar_expect(unsigned m, unsigned bytes) {
    asm volatile("mbarrier.arrive.expect_tx.shared.b64 _, [%0], %1;"
                 :: "r"(m), "r"(bytes) : "memory");
}
__device__ __forceinline__ void bulk_g2s(unsigned dst, const void* src,
                                         unsigned bytes, unsigned m) {
    asm volatile(
        "cp.async.bulk.shared::cluster.global.mbarrier::complete_tx::bytes "
        "[%0], [%1], %2, [%3];"
        :: "r"(dst), "l"(src), "r"(bytes), "r"(m) : "memory");
}
__device__ __forceinline__ void mbar_wait(unsigned m, unsigned parity) {
    asm volatile(
        "{\n\t.reg .pred P;\n\t"
        "WL_%=:\n\t"
        "mbarrier.try_wait.parity.acquire.cta.shared::cta.b64 P, [%0], %1;\n\t"
        "@P bra WD_%=;\n\t"
        "bra WL_%=;\n\t"
        "WD_%=:\n\t}"
        :: "r"(m), "r"(parity) : "memory");
}
__device__ __forceinline__ void fence_async() {
    asm volatile("fence.proxy.async.shared::cta;" ::: "memory");
}
__device__ __forceinline__ void batch_barrier(unsigned* cnt, int tid) {
    __threadfence();                         // release this block's stores
    __syncthreads();
    if (tid == 0) {
        unsigned o = atomicAdd(cnt, 1u);
        unsigned target = ((o >> 3) + 1u) << 3;   // next multiple of 8
        while ((int)(*(volatile unsigned*)cnt - target) < 0) __nanosleep(128);
        __threadfence();                     // acquire
    }
    __syncthreads();
}

// ============ fused kernel: grid = 512 = (batch, k), one wave ============
__global__ __launch_bounds__(256, 4) void k_fused(
    const float* __restrict__ x,
    const float* __restrict__ qk_w,
    const float* __restrict__ qk_b,
    const float* __restrict__ score_w,
    const float* __restrict__ score_b,
    const float* __restrict__ noise_x,
    const float* __restrict__ noise_r,
    float* __restrict__ out)
{
    // arena layout (byte offsets):
    //  A: slabs 0/1/2 at 0/15360/30720                       (46080)
    //  B: Msh 0..16640 (64x65 pad), rs4 @16640, ush4 @21760, tsm @25856
    //  C: dshA @0, dshB @4096, ash @8192, bshA/B @9216
    __shared__ __align__(128) unsigned char arena[46080];
    __shared__ __align__(8) unsigned long long mbar[3];
    __shared__ float qkb[128];

    int bi  = blockIdx.x;
    int b   = bi >> 3, k = bi & 7;
    int tid = threadIdx.x;
    int start = (k*30) >> 3, end = ((k+1)*30) >> 3;   // sizes 3,4,4,4,3,4,4,4
    int rows  = end - start;
    int hsA = c_hseg[start], hsB = c_hseg[end - 1];   // range spans <= 2 hsegs

    unsigned mb = s2u(mbar);
    if (tid == 0)
        for (int i = 0; i < 3; i++) mbar_init(mb + i*8, 1);
    if (tid < 128) qkb[tid] = qk_b[tid];
    float w0 = score_w[0], w1 = score_w[1], w2 = score_w[2];
    float sb = score_b[0];
    // noise preload (input-only): overlaps all phases
    int gi0 = (b*HH + start)*WW;
    float nxv = 0.f, nrv = 0.f;
    if (tid < rows*WW) { nxv = noise_x[gi0 + tid]; nrv = noise_r[gi0 + tid]; }
    __syncthreads();

    const char* xrow = (const char*)x + (size_t)(b*HH + start) * ROWB;

    // ---------------- phase A: balanced TMA cell partials -------------------
    {
        if (tid == 0) {
            int pre = rows < 3 ? rows : 3;
            for (int r = 0; r < pre; r++) {
                mbar_expect(mb + r*8, ROWB);
                bulk_g2s(s2u(arena + r*15360), xrow + (size_t)r*ROWB, ROWB, mb + r*8);
            }
        }
        int ws = tid >> 4, j = tid & 15;
        int a0i = c_wstart[ws], l0 = c_wlen[ws];
        float4 accA = make_float4(0.f,0.f,0.f,0.f);
        float4 accB = make_float4(0.f,0.f,0.f,0.f);
        #pragma unroll
        for (int r = 0; r < 4; r++) {
            if (r < rows) {
                int s = r % 3;
                mbar_wait(mb + s*8, r/3);
                const float4* sl = (const float4*)(arena + s*15360) + a0i*16 + j;
                float4 t = make_float4(0.f,0.f,0.f,0.f);
                #pragma unroll
                for (int w = 0; w < 6; w++) {
                    if (w < l0) {
                        float4 v = sl[w*16];
                        t.x += v.x; t.y += v.y; t.z += v.z; t.w += v.w;
                    }
                }
                if ((int)c_hseg[start + r] == hsA) {
                    accA.x += t.x; accA.y += t.y; accA.z += t.z; accA.w += t.w;
                } else {
                    accB.x += t.x; accB.y += t.y; accB.z += t.z; accB.w += t.w;
                }
                if (r + 3 < rows) {          // only rows=4, r=0: re-arm slab 0
                    __syncthreads();
                    if (tid == 0) {
                        fence_async();
                        mbar_expect(mb + s*8, ROWB);
                        bulk_g2s(s2u(arena + s*15360), xrow + (size_t)(r+3)*ROWB,
                                 ROWB, mb + s*8);
                    }
                }
            }
        }
        float4* pp = (float4*)(g_part + ((size_t)b*16 + k*2) * 1024);
        pp[ws*16 + j]       = accA;          // slot k*2
        pp[256 + ws*16 + j] = accB;          // slot k*2+1 (zeros if single-hseg)
    }

    batch_barrier(&g_cntA[b*32], tid);

    // ---------------- phase B: regions(f4) -> u -> t -> (s, dvec) -----------
    {
        float*  Msh  = (float*)arena;                    // 64x65 padded
        float4* rs4  = (float4*)(arena + 16640);         // 20 regions x 16 f4
        float4* ush4 = (float4*)(arena + 21760);         // 16 combos x 16 f4
        float*  tsm  = (float*)(arena + 25856);          // 16 x 64

        // Wk transposed, bank-padded: Msh[d*65+e] = Wk[e][d]
        for (int v = tid; v < 4096; v += 256) {
            int e = v >> 6, d = v & 63;
            Msh[d*65 + e] = qk_w[4096 + v];
        }

        // region sums (float4 gather over two partial slots per cell row)
        const float4* pb4 = (const float4*)(g_part + (size_t)b * 16384);
        int rh0 = c_rh0[k], rh1 = c_rh1[k], rh2 = c_rh2[k];
        for (int v = tid; v < 320; v += 256) {
            int jj = v >> 4, dq = v & 15;
            int hf, hc, wf, wc;
            if (jj < 10)      { hf=p0_hf[rh0]; hc=p0_hc[rh0]; wf=p0_wf[jj];   wc=p0_wc[jj]; }
            else if (jj < 16) { int rw=jj-10; hf=p1_hf[rh1]; hc=p1_hc[rh1]; wf=p1_wf[rw]; wc=p1_wc[rw]; }
            else              { int rw=jj-16; hf=p2_hf[rh2]; hc=p2_hc[rh2]; wf=p2_wf[rw]; wc=p2_wc[rw]; }
            float4 s = make_float4(0.f,0.f,0.f,0.f);
            for (int a = 0; a < hc; a++) {
                int hsr = hf + a;
                const float4* q1 = pb4 + (int)c_i1[hsr]*256;
                const float4* q2 = pb4 + (int)c_i2[hsr]*256;
                for (int c2 = 0; c2 < wc; c2++) {
                    int o = (wf + c2)*16 + dq;
                    float4 v1 = q1[o], v2 = q2[o];
                    s.x += v1.x + v2.x; s.y += v1.y + v2.y;
                    s.z += v1.z + v2.z; s.w += v1.w + v2.w;
                }
            }
            rs4[v] = s;
        }
        __syncthreads();

        float aw0 = w0*(1.f/36.f), aw1 = w1*(1.f/100.f), aw2 = w2*(1.f/225.f);
        float wsum = w0 + w1 + w2;

        // u[combo] (256 threads = 16 combos x 16 quads, exactly one each)
        {
            int wsg = tid >> 4, dq = tid & 15;
            float4 r0 = rs4[(int)c_rw0[wsg]*16 + dq];
            float4 r1 = rs4[(10 + (int)c_rw1[wsg])*16 + dq];
            float4 r2 = rs4[(16 + (int)c_rw2[wsg])*16 + dq];
            float4 u;
            u.x = aw0*r0.x + aw1*r1.x + aw2*r2.x;
            u.y = aw0*r0.y + aw1*r1.y + aw2*r2.y;
            u.z = aw0*r0.z + aw1*r1.z + aw2*r2.z;
            u.w = aw0*r0.w + aw1*r1.w + aw2*r2.w;
            ush4[tid] = u;
        }
        __syncthreads();

        // t[c] = Wk u[c] + wsum*bk   (thread = (e, 4-combo group))
        int e = tid & 63, cg = tid >> 6;
        {
            float init = wsum * qkb[64 + e];
            float t0 = init, t1 = init, t2 = init, t3 = init;
            #pragma unroll
            for (int fq = 0; fq < 16; fq++) {
                int d = fq*4;
                float m0 = Msh[(d+0)*65 + e];
                float m1 = Msh[(d+1)*65 + e];
                float m2 = Msh[(d+2)*65 + e];
                float m3 = Msh[(d+3)*65 + e];
                float4 ua = ush4[(cg*4 + 0)*16 + fq];
                float4 ub = ush4[(cg*4 + 1)*16 + fq];
                float4 uc = ush4[(cg*4 + 2)*16 + fq];
                float4 ud = ush4[(cg*4 + 3)*16 + fq];
                t0 += m0*ua.x + m1*ua.y + m2*ua.z + m3*ua.w;
                t1 += m0*ub.x + m1*ub.y + m2*ub.z + m3*ub.w;
                t2 += m0*uc.x + m1*uc.y + m2*uc.z + m3*uc.w;
                t3 += m0*ud.x + m1*ud.y + m2*ud.z + m3*ud.w;
            }
            tsm[(cg*4 + 0)*64 + e] = t0;
            tsm[(cg*4 + 1)*64 + e] = t1;
            tsm[(cg*4 + 2)*64 + e] = t2;
            tsm[(cg*4 + 3)*64 + e] = t3;
        }
        __syncthreads();

        // reload Msh with Wq (straight layout)
        for (int v = tid; v < 4096; v += 256) Msh[v] = qk_w[v];
        __syncthreads();

        // s[c] = bq . t[c]
        int lane = tid & 31, warp = tid >> 5;
        for (int c = warp; c < 16; c += 8) {
            float sv = tsm[c*64 + lane]      * qkb[lane]
                     + tsm[c*64 + 32 + lane] * qkb[32 + lane];
            #pragma unroll
            for (int o = 16; o; o >>= 1) sv += __shfl_xor_sync(0xffffffffu, sv, o);
            if (lane == 0) g_s[b*128 + k*16 + c] = sv;
        }

        // dvec[c] = Wq^T t[c] -> global
        {
            int jj = tid & 63;
            float d0 = 0.f, d1 = 0.f, d2 = 0.f, d3 = 0.f;
            const float4* t0p = (const float4*)(tsm + (cg*4 + 0)*64);
            const float4* t1p = (const float4*)(tsm + (cg*4 + 1)*64);
            const float4* t2p = (const float4*)(tsm + (cg*4 + 2)*64);
            const float4* t3p = (const float4*)(tsm + (cg*4 + 3)*64);
            #pragma unroll
            for (int eq = 0; eq < 16; eq++) {
                int ee = eq*4;
                float a0v = Msh[(ee+0)*64 + jj];
                float a1v = Msh[(ee+1)*64 + jj];
                float a2v = Msh[(ee+2)*64 + jj];
                float a3v = Msh[(ee+3)*64 + jj];
                float4 ta = t0p[eq], tb = t1p[eq], tc = t2p[eq], td = t3p[eq];
                d0 += a0v*ta.x + a1v*ta.y + a2v*ta.z + a3v*ta.w;
                d1 += a0v*tb.x + a1v*tb.y + a2v*tb.z + a3v*tb.w;
                d2 += a0v*tc.x + a1v*tc.y + a2v*tc.z + a3v*tc.w;
                d3 += a0v*td.x + a1v*td.y + a2v*td.z + a3v*td.w;
            }
            float* dst = g_dvec + ((size_t)(b*8 + k)*16 + cg*4)*64;
            dst[0*64 + jj] = d0;
            dst[1*64 + jj] = d1;
            dst[2*64 + jj] = d2;
            dst[3*64 + jj] = d3;
        }
    }

    batch_barrier(&g_cntB[b*32], tid);

    // ---------------- phase C: direct-L2 dot + gumbel, sync-free rows -------
    {
        float4* dshA4 = (float4*)arena;
        float4* dshB4 = (float4*)(arena + 4096);
        float*  ashp  = (float*)(arena + 8192);          // rows*60 <= 240
        float*  bshA  = (float*)(arena + 9216);
        float*  bshB  = bshA + 16;

        const float4* srcA = (const float4*)(g_dvec + (size_t)(b*8 + hsA)*1024);
        const float4* srcB = (const float4*)(g_dvec + (size_t)(b*8 + hsB)*1024);
        dshA4[tid] = srcA[tid];              // 256 f4 = full 16x64 each
        dshB4[tid] = srcB[tid];
        if (tid < 16) {
            bshA[tid] = 0.125f * g_s[b*128 + hsA*16 + tid] + sb;
            bshB[tid] = 0.125f * g_s[b*128 + hsB*16 + tid] + sb;
        }
        __syncthreads();

        int lane = tid & 31, warp = tid >> 5;
        int half = lane >> 4, jq = lane & 15;
        int p0 = warp*2 + half;              // 0..15
        const float4* xb4 = (const float4*)xrow;   // rows x 60 x 16 f4 (L2-hot)

        #pragma unroll
        for (int r = 0; r < 4; r++) {
            if (r < rows) {
                bool isA = ((int)c_hseg[start + r] == hsA);
                const float4* dsm = isA ? dshA4 : dshB4;
                const float*  bs  = isA ? bshA  : bshB;
                const float4* xs4 = xb4 + r*(WW*16);
                #pragma unroll
                for (int it = 0; it < 4; it++) {
                    int p = p0 + it*16;
                    float dot = 0.f; int wsg = 0;
                    if (p < WW) {
                        wsg = c_wseg[p];
                        float4 a = xs4[p*16 + jq];       // 256B/half-warp coalesced
                        float4 d = dsm[wsg*16 + jq];
                        dot = a.x*d.x + a.y*d.y + a.z*d.z + a.w*d.w;
                    }
                    #pragma unroll
                    for (int o = 1; o < 16; o <<= 1)
                        dot += __shfl_xor_sync(0xffffffffu, dot, o);
                    if (p < WW && jq == 0) ashp[r*WW + p] = 0.125f*dot + bs[wsg];
                }
            }
        }
        __syncthreads();

        if (tid < rows*WW) {
            float attn = ashp[tid];
            // log(sig+eps) - log(1-sig+eps) == attn  (|attn| small; err ~1e-6)
            float nx = -logf(-logf(nxv + 1e-8f) + 1e-8f);
            float nr = -logf(-logf(nrv + 1e-8f) + 1e-8f);
            const float invT = 1.f / (0.03f + 1e-8f);
            float l = (attn + nx - nr) * invT;
            out[gi0 + tid] = 1.f / (1.f + expf(-l));
        }
    }
}

// ---------------- launcher ----------------
extern "C" void kernel_launch(void* const* d_in, const int* in_sizes, int n_in,
                              void* d_out, int out_size) {
    const float* x       = (const float*)d_in[0];   // (64,30,60,64)
    const float* qk_w    = (const float*)d_in[1];   // (128,64)
    const float* qk_b    = (const float*)d_in[2];   // (128,)
    const float* score_w = (const float*)d_in[3];   // (1,3)
    const float* score_b = (const float*)d_in[4];   // (1,)
    const float* noise_x = (const float*)d_in[5];   // (64,1800,1)
    const float* noise_r = (const float*)d_in[6];   // (64,1800,1)
    float* out = (float*)d_out;                     // (64,1800,1)

    k_fused<<<NB*8, 256>>>(x, qk_w, qk_b, score_w, score_b,
                           noise_x, noise_r, out);
}